// round 1
// baseline (speedup 1.0000x reference)
#include <cuda_runtime.h>
#include <math_constants.h>

#define BLOCK 256
#define WSH_F2 12032                 // max weight buffer: (188/2)*128 float2
#define ACT_F2 (64 * BLOCK)          // 64 feature-pairs x 256 threads
#define SMEM_BYTES ((WSH_F2 + ACT_F2) * 8)

union F2U { float2 f; unsigned long long u; };

__device__ __forceinline__ float2 ffma2(float2 a, float2 b, float2 c) {
    F2U ua, ub, uc, ud;
    ua.f = a; ub.f = b; uc.f = c;
    asm("fma.rn.f32x2 %0, %1, %2, %3;"
        : "=l"(ud.u) : "l"(ua.u), "l"(ub.u), "l"(uc.u));
    return ud.f;
}

__device__ __forceinline__ float2 mk2(float x, float y) { return make_float2(x, y); }

// Stage weights [K][OUT] (row-major, global) into shared as k-pair-interleaved:
// wsh[kk*OUTP + j] = (W[2kk][jm], W[2kk+1][jm]).
// ROT (for Wd2_3, OUT=129): jm = j+1 for j<128 (features), jm=0 at j==128 (blending),
// zero-pad beyond. Coalesced: consecutive tid -> consecutive j -> contiguous gmem.
template<int K, int OUT, int OUTP, bool ROT>
__device__ __forceinline__ void stage(float2* wsh, const float* __restrict__ W) {
    constexpr int KH = K / 2;
    for (int idx = threadIdx.x; idx < KH * OUTP; idx += BLOCK) {
        int kk = idx / OUTP;
        int j  = idx - kk * OUTP;
        int jm;
        if (ROT) jm = (j < OUT - 1) ? (j + 1) : ((j == OUT - 1) ? 0 : -1);
        else     jm = (j < OUT) ? j : -1;
        float a = 0.f, b = 0.f;
        if (jm >= 0) {
            a = W[(2 * kk)     * OUT + jm];
            b = W[(2 * kk + 1) * OUT + jm];
        }
        wsh[idx] = make_float2(a, b);
    }
}

// One layer: out[j] = sum_k h[k]*W[k][j], h = [reg-pair prefix rp (KHR pairs)] ++
// [shared act (KHS pairs, this thread's column)]. j-tile of 8 -> 8 independent
// packed accumulator chains. Results go to register array out2 (4 float2 per tile).
template<int KHR, int KHS, int NTILE, bool RELU>
__device__ __forceinline__ void run_layer(const float2* rp,
                                          const float2* __restrict__ wsh,
                                          const float2* __restrict__ actS,
                                          int tid, float2* out2) {
    constexpr int OUTH = NTILE * 4;   // float4 per weight row (OUTP/2 float4)
    const float4* wall = reinterpret_cast<const float4*>(wsh);
#pragma unroll
    for (int t = 0; t < NTILE; t++) {
        float2 a0 = mk2(0.f, 0.f), a1 = a0, a2 = a0, a3 = a0;
        float2 a4 = a0, a5 = a0, a6 = a0, a7 = a0;
        const float4* wb = wall + 4 * t;
#pragma unroll
        for (int r = 0; r < KHR; r++) {
            float2 v = rp[r];
            const float4* w = wb + r * OUTH;
            float4 q0 = w[0], q1 = w[1], q2 = w[2], q3 = w[3];
            a0 = ffma2(v, mk2(q0.x, q0.y), a0);
            a1 = ffma2(v, mk2(q0.z, q0.w), a1);
            a2 = ffma2(v, mk2(q1.x, q1.y), a2);
            a3 = ffma2(v, mk2(q1.z, q1.w), a3);
            a4 = ffma2(v, mk2(q2.x, q2.y), a4);
            a5 = ffma2(v, mk2(q2.z, q2.w), a5);
            a6 = ffma2(v, mk2(q3.x, q3.y), a6);
            a7 = ffma2(v, mk2(q3.z, q3.w), a7);
        }
#pragma unroll 4
        for (int k = 0; k < KHS; k++) {
            float2 v = actS[k * BLOCK + tid];
            const float4* w = wb + (KHR + k) * OUTH;
            float4 q0 = w[0], q1 = w[1], q2 = w[2], q3 = w[3];
            a0 = ffma2(v, mk2(q0.x, q0.y), a0);
            a1 = ffma2(v, mk2(q0.z, q0.w), a1);
            a2 = ffma2(v, mk2(q1.x, q1.y), a2);
            a3 = ffma2(v, mk2(q1.z, q1.w), a3);
            a4 = ffma2(v, mk2(q2.x, q2.y), a4);
            a5 = ffma2(v, mk2(q2.z, q2.w), a5);
            a6 = ffma2(v, mk2(q3.x, q3.y), a6);
            a7 = ffma2(v, mk2(q3.z, q3.w), a7);
        }
        float r0 = a0.x + a0.y, r1 = a1.x + a1.y, r2 = a2.x + a2.y, r3 = a3.x + a3.y;
        float r4 = a4.x + a4.y, r5 = a5.x + a5.y, r6 = a6.x + a6.y, r7 = a7.x + a7.y;
        if (RELU) {
            r0 = fmaxf(r0, 0.f); r1 = fmaxf(r1, 0.f); r2 = fmaxf(r2, 0.f); r3 = fmaxf(r3, 0.f);
            r4 = fmaxf(r4, 0.f); r5 = fmaxf(r5, 0.f); r6 = fmaxf(r6, 0.f); r7 = fmaxf(r7, 0.f);
        }
        out2[4 * t + 0] = mk2(r0, r1);
        out2[4 * t + 1] = mk2(r2, r3);
        out2[4 * t + 2] = mk2(r4, r5);
        out2[4 * t + 3] = mk2(r6, r7);
    }
}

__device__ __forceinline__ void store_act(float2* actS, const float2* out2, int tid) {
#pragma unroll
    for (int k = 0; k < 64; k++) actS[k * BLOCK + tid] = out2[k];
}

__global__ void __launch_bounds__(BLOCK, 1)
nerf_fused_kernel(const float* __restrict__ x,
                  const float* __restrict__ Wd1_0, const float* __restrict__ Wd1_1,
                  const float* __restrict__ Wd1_2, const float* __restrict__ Wd2_0,
                  const float* __restrict__ Wd2_1, const float* __restrict__ Wd2_2,
                  const float* __restrict__ Wd2_3, const float* __restrict__ Wc_0,
                  const float* __restrict__ Wc_1,  float* __restrict__ out, int N) {
    extern __shared__ float4 smem_raw[];
    float2* wsh  = reinterpret_cast<float2*>(smem_raw);
    float2* actS = wsh + WSH_F2;

    const int tid = threadIdx.x;
    const int i = blockIdx.x * BLOCK + tid;

    float px = 0.f, py = 0.f, pz = 0.f, vx = 0.f, vy = 0.f, vz = 0.f;
    if (i < N) {
        const float* xp = x + 6 * i;
        px = xp[0]; py = xp[1]; pz = xp[2];
        vx = xp[3]; vy = xp[4]; vz = xp[5];
    }

    // Positional encoding: ep[d*10+f] = (sin, cos)(pos_d * pi * 2^f)
    float2 ep[30];
#pragma unroll
    for (int d = 0; d < 3; d++) {
        float base = (d == 0) ? px : ((d == 1) ? py : pz);
#pragma unroll
        for (int f = 0; f < 10; f++) {
            float s, c;
            sincosf(base * (CUDART_PI_F * (float)(1 << f)), &s, &c);
            ep[d * 10 + f] = mk2(s, c);
        }
    }

    float2 out2[68];

    // ---- L1: enc_pos(60) -> 128, relu ----
    stage<60, 128, 128, false>(wsh, Wd1_0);
    __syncthreads();
    run_layer<30, 0, 16, true>(ep, wsh, actS, tid, out2);
    store_act(actS, out2, tid);

    // ---- L2: 128 -> 128, relu ----
    __syncthreads();
    stage<128, 128, 128, false>(wsh, Wd1_1);
    __syncthreads();
    run_layer<0, 64, 16, true>(nullptr, wsh, actS, tid, out2);
    store_act(actS, out2, tid);

    // ---- L3: 128 -> 128, linear (part1) ----
    __syncthreads();
    stage<128, 128, 128, false>(wsh, Wd1_2);
    __syncthreads();
    run_layer<0, 64, 16, false>(nullptr, wsh, actS, tid, out2);
    store_act(actS, out2, tid);

    // ---- L4: concat(enc_pos 60, part1 128) = 188 -> 128, relu ----
    __syncthreads();
    stage<188, 128, 128, false>(wsh, Wd2_0);
    __syncthreads();
    run_layer<30, 64, 16, true>(ep, wsh, actS, tid, out2);
    store_act(actS, out2, tid);

    // ---- L5: 128 -> 128, relu ----
    __syncthreads();
    stage<128, 128, 128, false>(wsh, Wd2_1);
    __syncthreads();
    run_layer<0, 64, 16, true>(nullptr, wsh, actS, tid, out2);
    store_act(actS, out2, tid);

    // ---- L6: 128 -> 128, relu ----
    __syncthreads();
    stage<128, 128, 128, false>(wsh, Wd2_2);
    __syncthreads();
    run_layer<0, 64, 16, true>(nullptr, wsh, actS, tid, out2);
    store_act(actS, out2, tid);

    // ---- L7: 128 -> 129, linear. Columns rotated at staging: j=0..127 are
    // feature[0..127], j=128 is the blending column (orig col 0). ----
    __syncthreads();
    stage<128, 129, 136, true>(wsh, Wd2_3);
    __syncthreads();
    run_layer<0, 64, 17, false>(nullptr, wsh, actS, tid, out2);
    float density      = out2[0].x;    // feature[0], raw
    float blending_raw = out2[64].x;   // pre-sigmoid
    store_act(actS, out2, tid);        // feature -> actS

    // View encoding: ev[d*4+f] = (sin, cos)(view_d * pi * 2^f)
    float2 ev[12];
#pragma unroll
    for (int d = 0; d < 3; d++) {
        float base = (d == 0) ? vx : ((d == 1) ? vy : vz);
#pragma unroll
        for (int f = 0; f < 4; f++) {
            float s, c;
            sincosf(base * (CUDART_PI_F * (float)(1 << f)), &s, &c);
            ev[d * 4 + f] = mk2(s, c);
        }
    }

    // ---- L8: concat(enc_view 24, feature 128) = 152 -> 128, relu ----
    __syncthreads();
    stage<152, 128, 128, false>(wsh, Wc_0);
    __syncthreads();
    run_layer<12, 64, 16, true>(ev, wsh, actS, tid, out2);
    store_act(actS, out2, tid);

    // ---- L9: 128 -> 3, linear (rgb) ----
    __syncthreads();
    stage<128, 3, 8, false>(wsh, Wc_1);
    __syncthreads();
    run_layer<0, 64, 1, false>(nullptr, wsh, actS, tid, out2);
    float rgb0 = out2[0].x, rgb1 = out2[0].y, rgb2 = out2[1].x;

    if (i < N) {
        float blending = 1.f / (1.f + expf(-blending_raw));
        float* o = out + 5 * i;
        o[0] = rgb0;
        o[1] = rgb1;
        o[2] = rgb2;
        o[3] = density;
        o[4] = blending;
    }
}

extern "C" void kernel_launch(void* const* d_in, const int* in_sizes, int n_in,
                              void* d_out, int out_size) {
    const float* x     = (const float*)d_in[0];
    const float* Wd1_0 = (const float*)d_in[1];
    const float* Wd1_1 = (const float*)d_in[2];
    const float* Wd1_2 = (const float*)d_in[3];
    const float* Wd2_0 = (const float*)d_in[4];
    const float* Wd2_1 = (const float*)d_in[5];
    const float* Wd2_2 = (const float*)d_in[6];
    const float* Wd2_3 = (const float*)d_in[7];
    const float* Wc_0  = (const float*)d_in[8];
    const float* Wc_1  = (const float*)d_in[9];
    float* out = (float*)d_out;

    int N = in_sizes[0] / 6;
    if (N <= 0) return;

    cudaFuncSetAttribute(nerf_fused_kernel,
                         cudaFuncAttributeMaxDynamicSharedMemorySize, SMEM_BYTES);

    int grid = (N + BLOCK - 1) / BLOCK;
    nerf_fused_kernel<<<grid, BLOCK, SMEM_BYTES>>>(
        x, Wd1_0, Wd1_1, Wd1_2, Wd2_0, Wd2_1, Wd2_2, Wd2_3, Wc_0, Wc_1, out, N);
}

// round 3
// speedup vs baseline: 1.3970x; 1.3970x over previous
#include <cuda_runtime.h>
#include <math_constants.h>

#define BLOCK 256
#define PTS   128
#define SROW  130              // act row stride in float2 (conflict-free stores)
#define SV4   65               // act row stride in float4

#define WSH_F4  6016           // 94 k-pairs * 64 out-pairs
#define ACT_F4  (64 * SV4)     // 4160
#define ENCP_F4 (30 * SV4)     // 1950
#define ENCV_F4 (12 * SV4)     // 780
#define BCOL_F4 32             // 64 float2
#define AUX_F4  64             // blend[128] + dens[128] floats
#define SMEM_F4 (WSH_F4 + ACT_F4 + ENCP_F4 + ENCV_F4 + BCOL_F4 + AUX_F4)
#define SMEM_BYTES (SMEM_F4 * 16)   // 208,032 B -> 1 block/SM

union F2U { float2 f; unsigned long long u; };

__device__ __forceinline__ float2 ffma2(float2 a, float2 b, float2 c) {
    F2U ua, ub, uc, ud;
    ua.f = a; ub.f = b; uc.f = c;
    asm("fma.rn.f32x2 %0, %1, %2, %3;"
        : "=l"(ud.u) : "l"(ua.u), "l"(ub.u), "l"(uc.u));
    return ud.f;
}
__device__ __forceinline__ float2 mk2(float x, float y) { return make_float2(x, y); }

// Stage W[K][OUT] as float4(W[2kk][c0], W[2kk+1][c0], W[2kk][c0+1], W[2kk+1][c0+1])
// at wsh4[kk*64 + jp], c0 = 2*jp + COLOFF. COLOFF=1 rotates Wd2_3 (col0=blending
// handled separately) so logical out j = feature[j].
template<int KH, int OUT, int COLOFF>
__device__ __forceinline__ void stageW(float4* wsh4, const float* __restrict__ W) {
    for (int idx = threadIdx.x; idx < KH * 64; idx += BLOCK) {
        int kk = idx >> 6, jp = idx & 63;
        int c0 = 2 * jp + COLOFF;
        const float* r0 = W + (2 * kk) * OUT + c0;
        const float* r1 = W + (2 * kk + 1) * OUT + c0;
        wsh4[idx] = make_float4(r0[0], r1[0], r0[1], r1[1]);
    }
}

__device__ __forceinline__ void zeroAcc(float2 (&A0)[4][8], float2 (&A1)[4][8]) {
#pragma unroll
    for (int q = 0; q < 4; q++)
#pragma unroll
        for (int p = 0; p < 8; p++) { A0[q][p] = mk2(0.f, 0.f); A1[q][p] = mk2(0.f, 0.f); }
}

// GEMM accumulate: 8 points (pg*8..+7) x 8 outputs (pairs jg+16q) over KH k-pairs.
template<int KH>
__device__ __forceinline__ void accum(const float2* __restrict__ actB,
                                      const float4* __restrict__ wB,
                                      int pg, int jg,
                                      float2 (&A0)[4][8], float2 (&A1)[4][8]) {
    const float4* av = reinterpret_cast<const float4*>(actB) + pg * 4;
#pragma unroll 4
    for (int kk = 0; kk < KH; kk++) {
        float4 b0 = av[kk * SV4 + 0], b1 = av[kk * SV4 + 1];
        float4 b2 = av[kk * SV4 + 2], b3 = av[kk * SV4 + 3];
        float2 ap[8] = { mk2(b0.x,b0.y), mk2(b0.z,b0.w), mk2(b1.x,b1.y), mk2(b1.z,b1.w),
                         mk2(b2.x,b2.y), mk2(b2.z,b2.w), mk2(b3.x,b3.y), mk2(b3.z,b3.w) };
#pragma unroll
        for (int q = 0; q < 4; q++) {
            float4 w = wB[kk * 64 + jg + 16 * q];
            float2 w0 = mk2(w.x, w.y), w1 = mk2(w.z, w.w);
#pragma unroll
            for (int p = 0; p < 8; p++) {
                A0[q][p] = ffma2(ap[p], w0, A0[q][p]);
                A1[q][p] = ffma2(ap[p], w1, A1[q][p]);
            }
        }
    }
}

template<bool RELU>
__device__ __forceinline__ void storeAct(float2* act2, int pg, int jg,
                                         float2 (&A0)[4][8], float2 (&A1)[4][8]) {
#pragma unroll
    for (int q = 0; q < 4; q++) {
        int jp = jg + 16 * q;
        float4* dst = reinterpret_cast<float4*>(act2 + jp * SROW + pg * 8);
#pragma unroll
        for (int u = 0; u < 4; u++) {
            int p = 2 * u;
            float r0 = A0[q][p].x + A0[q][p].y;
            float r1 = A1[q][p].x + A1[q][p].y;
            float r2 = A0[q][p + 1].x + A0[q][p + 1].y;
            float r3 = A1[q][p + 1].x + A1[q][p + 1].y;
            if (RELU) {
                r0 = fmaxf(r0, 0.f); r1 = fmaxf(r1, 0.f);
                r2 = fmaxf(r2, 0.f); r3 = fmaxf(r3, 0.f);
            }
            dst[u] = make_float4(r0, r1, r2, r3);
        }
    }
}

__global__ void __launch_bounds__(BLOCK, 1)
nerf_gemm_kernel(const float* __restrict__ x,
                 const float* __restrict__ Wd1_0, const float* __restrict__ Wd1_1,
                 const float* __restrict__ Wd1_2, const float* __restrict__ Wd2_0,
                 const float* __restrict__ Wd2_1, const float* __restrict__ Wd2_2,
                 const float* __restrict__ Wd2_3, const float* __restrict__ Wc_0,
                 const float* __restrict__ Wc_1,  float* __restrict__ out, int N) {
    extern __shared__ float4 sm[];
    float4* wsh4   = sm;
    float2* act2   = reinterpret_cast<float2*>(sm + WSH_F4);
    float2* encP   = reinterpret_cast<float2*>(sm + WSH_F4 + ACT_F4);
    float2* encV   = reinterpret_cast<float2*>(sm + WSH_F4 + ACT_F4 + ENCP_F4);
    float2* bcol2  = reinterpret_cast<float2*>(sm + WSH_F4 + ACT_F4 + ENCP_F4 + ENCV_F4);
    float*  blendS = reinterpret_cast<float*>(sm + WSH_F4 + ACT_F4 + ENCP_F4 + ENCV_F4 + BCOL_F4);
    float*  densS  = blendS + 128;
    float*  wshF   = reinterpret_cast<float*>(wsh4);

    const int t  = threadIdx.x;
    const int pg = t >> 4;        // point group: points pg*8 .. pg*8+7
    const int jg = t & 15;        // output-pair group: jp = jg + 16q
    const int i0 = blockIdx.x * PTS;

    // ---- encodings (threads 0..127, one point each) ----
    if (t < PTS) {
        int i = i0 + t;
        float xv[6];
#pragma unroll
        for (int c = 0; c < 6; c++) xv[c] = (i < N) ? x[6 * i + c] : 0.f;
#pragma unroll
        for (int d = 0; d < 3; d++)
#pragma unroll
            for (int f = 0; f < 10; f++) {
                float s, c;
                sincosf(xv[d] * (CUDART_PI_F * (float)(1 << f)), &s, &c);
                encP[(d * 10 + f) * SROW + t] = mk2(s, c);
            }
#pragma unroll
        for (int d = 0; d < 3; d++)
#pragma unroll
            for (int f = 0; f < 4; f++) {
                float s, c;
                sincosf(xv[3 + d] * (CUDART_PI_F * (float)(1 << f)), &s, &c);
                encV[(d * 4 + f) * SROW + t] = mk2(s, c);
            }
    }

    float2 A0[4][8], A1[4][8];

    // ---- L1: enc_pos(60) -> 128, relu ----
    stageW<30, 128, 0>(wsh4, Wd1_0);
    __syncthreads();                              // enc + weights visible
    zeroAcc(A0, A1);
    accum<30>(encP, wsh4, pg, jg, A0, A1);
    storeAct<true>(act2, pg, jg, A0, A1);         // act has no readers yet

    // ---- L2: 128 -> 128, relu ----
    __syncthreads();
    stageW<64, 128, 0>(wsh4, Wd1_1);
    __syncthreads();
    zeroAcc(A0, A1);
    accum<64>(act2, wsh4, pg, jg, A0, A1);
    __syncthreads();
    storeAct<true>(act2, pg, jg, A0, A1);

    // ---- L3: 128 -> 128, linear (part1) ----
    __syncthreads();
    stageW<64, 128, 0>(wsh4, Wd1_2);
    __syncthreads();
    zeroAcc(A0, A1);
    accum<64>(act2, wsh4, pg, jg, A0, A1);
    __syncthreads();
    storeAct<false>(act2, pg, jg, A0, A1);

    // ---- L4: concat(enc_pos 60, part1 128) -> 128, relu ----
    __syncthreads();
    stageW<94, 128, 0>(wsh4, Wd2_0);
    __syncthreads();
    zeroAcc(A0, A1);
    accum<30>(encP, wsh4, pg, jg, A0, A1);
    accum<64>(act2, wsh4 + 30 * 64, pg, jg, A0, A1);
    __syncthreads();
    storeAct<true>(act2, pg, jg, A0, A1);

    // ---- L5: 128 -> 128, relu ----
    __syncthreads();
    stageW<64, 128, 0>(wsh4, Wd2_1);
    __syncthreads();
    zeroAcc(A0, A1);
    accum<64>(act2, wsh4, pg, jg, A0, A1);
    __syncthreads();
    storeAct<true>(act2, pg, jg, A0, A1);

    // ---- L6: 128 -> 128, relu ----
    __syncthreads();
    stageW<64, 128, 0>(wsh4, Wd2_2);
    __syncthreads();
    zeroAcc(A0, A1);
    accum<64>(act2, wsh4, pg, jg, A0, A1);
    __syncthreads();
    storeAct<true>(act2, pg, jg, A0, A1);

    // ---- L7: 128 -> 129, linear. Rotated: logical j = feature[j]; col0=blending ----
    __syncthreads();
    stageW<64, 129, 1>(wsh4, Wd2_3);
    if (t < 64)
        bcol2[t] = mk2(Wd2_3[(2 * t) * 129], Wd2_3[(2 * t + 1) * 129]);
    __syncthreads();
    zeroAcc(A0, A1);
    accum<64>(act2, wsh4, pg, jg, A0, A1);
    if (t < PTS) {                                // blending (reads L6 act)
        float2 bacc = mk2(0.f, 0.f);
#pragma unroll 4
        for (int kk = 0; kk < 64; kk++)
            bacc = ffma2(act2[kk * SROW + t], bcol2[kk], bacc);
        blendS[t] = bacc.x + bacc.y;
    }
    __syncthreads();
    storeAct<false>(act2, pg, jg, A0, A1);
    if (jg == 0) {                                // density = feature[0] (linear)
#pragma unroll
        for (int p = 0; p < 8; p++)
            densS[pg * 8 + p] = A0[0][p].x + A0[0][p].y;
    }

    // ---- L8: concat(enc_view 24, feature 128) -> 128, relu ----
    __syncthreads();
    stageW<76, 128, 0>(wsh4, Wc_0);
    __syncthreads();
    zeroAcc(A0, A1);
    accum<12>(encV, wsh4, pg, jg, A0, A1);
    accum<64>(act2, wsh4 + 12 * 64, pg, jg, A0, A1);
    __syncthreads();
    storeAct<true>(act2, pg, jg, A0, A1);

    // ---- L9: 128 -> 3 (rgb), then final writeout ----
    __syncthreads();
    for (int idx = t; idx < 384; idx += BLOCK)    // FIX: 384 > BLOCK, must stride
        wshF[idx] = Wc_1[idx];
    __syncthreads();
    if (t < PTS) {
        int i = i0 + t;
        float r0 = 0.f, r1 = 0.f, r2 = 0.f;
#pragma unroll 4
        for (int kk = 0; kk < 64; kk++) {
            float2 h = act2[kk * SROW + t];
            r0 = fmaf(h.x, wshF[(2 * kk) * 3 + 0], r0);
            r1 = fmaf(h.x, wshF[(2 * kk) * 3 + 1], r1);
            r2 = fmaf(h.x, wshF[(2 * kk) * 3 + 2], r2);
            r0 = fmaf(h.y, wshF[(2 * kk + 1) * 3 + 0], r0);
            r1 = fmaf(h.y, wshF[(2 * kk + 1) * 3 + 1], r1);
            r2 = fmaf(h.y, wshF[(2 * kk + 1) * 3 + 2], r2);
        }
        if (i < N) {
            float* o = out + 5 * i;
            o[0] = r0;
            o[1] = r1;
            o[2] = r2;
            o[3] = densS[t];
            o[4] = 1.f / (1.f + expf(-blendS[t]));
        }
    }
}

extern "C" void kernel_launch(void* const* d_in, const int* in_sizes, int n_in,
                              void* d_out, int out_size) {
    const float* x     = (const float*)d_in[0];
    const float* Wd1_0 = (const float*)d_in[1];
    const float* Wd1_1 = (const float*)d_in[2];
    const float* Wd1_2 = (const float*)d_in[3];
    const float* Wd2_0 = (const float*)d_in[4];
    const float* Wd2_1 = (const float*)d_in[5];
    const float* Wd2_2 = (const float*)d_in[6];
    const float* Wd2_3 = (const float*)d_in[7];
    const float* Wc_0  = (const float*)d_in[8];
    const float* Wc_1  = (const float*)d_in[9];
    float* out = (float*)d_out;

    int N = in_sizes[0] / 6;
    if (N <= 0) return;

    cudaFuncSetAttribute(nerf_gemm_kernel,
                         cudaFuncAttributeMaxDynamicSharedMemorySize, SMEM_BYTES);

    int grid = (N + PTS - 1) / PTS;
    nerf_gemm_kernel<<<grid, BLOCK, SMEM_BYTES>>>(
        x, Wd1_0, Wd1_1, Wd1_2, Wd2_0, Wd2_1, Wd2_2, Wd2_3, Wc_0, Wc_1, out, N);
}

// round 6
// speedup vs baseline: 3.0596x; 2.1902x over previous
#include <cuda_runtime.h>
#include <cuda_bf16.h>
#include <math_constants.h>
#include <cstdint>

#define BLOCK 256
#define PTS   128

// ---- smem byte offsets ----
#define AHI_OFF   0         // act hi  [128][136] bf16 (stride 272B) = 34816
#define ALO_OFF   34816     // act lo
#define EHI_OFF   69632     // enc hi  [128][72] bf16 (stride 144B) = 18432
#define ELO_OFF   88064     // enc lo  (= EHI + 18432; was the R5 overlap bug)
#define BHI_OFF   106496    // weight hi, max 200*128*2 = 51200B
#define BLO_OFF   157696    // weight lo
#define WC1_OFF   208896    // Wc_1 fp32 [128][3]
#define BCOL_OFF  210432    // Wd2_3 col0 fp32 [128]
#define DENS_OFF  210944    // density fp32 [128]
#define PB_OFF    211456    // blend raw fp32 [128]
#define PR_OFF    211968    // rgb fp32 [128][3]
#define SMEM_BYTES 213504

#define SA 272              // act row stride bytes (136 bf16)
#define SE 144              // enc row stride bytes (72 bf16)
#define BLO_DELTA 51200
#define ALO_DELTA 34816
#define ELO_DELTA 18432

// ---- pre-converted weights: Bt[j][k] row-major, padded, bf16 hi/lo ----
// per-layer padded K: {72,136,136,200,136,136,136,168}, rows 128
__device__ __nv_bfloat16 g_whi[143360];
__device__ __nv_bfloat16 g_wlo[143360];

__constant__ int c_loff[9] = {0, 9216, 26624, 44032, 69632, 87040, 104448, 121856, 143360};
__constant__ int c_kpad[8] = {72, 136, 136, 200, 136, 136, 136, 168};
__constant__ int c_sB[8]   = {144, 272, 272, 400, 272, 272, 272, 336};
__constant__ int c_encKt[8] = {4, 0, 0, 4, 0, 0, 0, 2};
__constant__ int c_actKt[8] = {0, 8, 8, 8, 8, 8, 8, 8};
__constant__ int c_n16[8]  = {1152, 2176, 2176, 3200, 2176, 2176, 2176, 2688};

__global__ void prepass_kernel(const float* __restrict__ Wd1_0, const float* __restrict__ Wd1_1,
                               const float* __restrict__ Wd1_2, const float* __restrict__ Wd2_0,
                               const float* __restrict__ Wd2_1, const float* __restrict__ Wd2_2,
                               const float* __restrict__ Wd2_3, const float* __restrict__ Wc_0) {
    int e = blockIdx.x * blockDim.x + threadIdx.x;
    if (e >= 143360) return;
    int l = 0;
    while (e >= c_loff[l + 1]) l++;
    int r = e - c_loff[l];
    int kp = c_kpad[l];
    int j = r / kp;          // B row (output index), 0..127
    int k = r % kp;          // K index (incl. pad)
    float v = 0.f;
    switch (l) {
        case 0: if (k < 60) v = Wd1_0[k * 128 + j]; break;
        case 1: if (k < 128) v = Wd1_1[k * 128 + j]; break;
        case 2: if (k < 128) v = Wd1_2[k * 128 + j]; break;
        case 3: if (k < 60) v = Wd2_0[k * 128 + j];
                else if (k >= 64 && k < 192) v = Wd2_0[(k - 4) * 128 + j];
                break;
        case 4: if (k < 128) v = Wd2_1[k * 128 + j]; break;
        case 5: if (k < 128) v = Wd2_2[k * 128 + j]; break;
        case 6: if (k < 128) v = Wd2_3[k * 129 + (j + 1)]; break;  // rotated: j = feature[j]
        case 7: if (k < 24) v = Wc_0[k * 128 + j];
                else if (k >= 32 && k < 160) v = Wc_0[(k - 8) * 128 + j];
                break;
    }
    __nv_bfloat16 hi = __float2bfloat16(v);
    __nv_bfloat16 lo = __float2bfloat16(v - __bfloat162float(hi));
    g_whi[e] = hi;
    g_wlo[e] = lo;
}

// ---- helpers ----
__device__ __forceinline__ void mma16816(float* d, const uint32_t* a, const uint32_t* b) {
    asm volatile(
        "mma.sync.aligned.m16n8k16.row.col.f32.bf16.bf16.f32 "
        "{%0,%1,%2,%3}, {%4,%5,%6,%7}, {%8,%9}, {%0,%1,%2,%3};"
        : "+f"(d[0]), "+f"(d[1]), "+f"(d[2]), "+f"(d[3])
        : "r"(a[0]), "r"(a[1]), "r"(a[2]), "r"(a[3]), "r"(b[0]), "r"(b[1]));
}

__device__ __forceinline__ uint32_t packSplitHi(float f0, float f1, uint32_t& lp) {
    __nv_bfloat16 h0 = __float2bfloat16(f0), h1 = __float2bfloat16(f1);
    __nv_bfloat16 l0 = __float2bfloat16(f0 - __bfloat162float(h0));
    __nv_bfloat16 l1 = __float2bfloat16(f1 - __bfloat162float(h1));
    lp = ((uint32_t)__bfloat16_as_ushort(l1) << 16) | __bfloat16_as_ushort(l0);
    return ((uint32_t)__bfloat16_as_ushort(h1) << 16) | __bfloat16_as_ushort(h0);
}

__device__ __forceinline__ void encStore(char* sm, int row, int col, float f0, float f1) {
    uint32_t lp, hp = packSplitHi(f0, f1, lp);
    *reinterpret_cast<uint32_t*>(sm + EHI_OFF + row * SE + col * 2) = hp;
    *reinterpret_cast<uint32_t*>(sm + ELO_OFF + row * SE + col * 2) = lp;
}

__global__ void __launch_bounds__(BLOCK, 1)
nerf_mma_kernel(const float* __restrict__ x, const float* __restrict__ Wd2_3,
                const float* __restrict__ Wc_1, float* __restrict__ out, int N) {
    extern __shared__ char sm[];
    const int t = threadIdx.x;
    const int w = t >> 5, lane = t & 31;
    const int q = lane & 3, rh = lane >> 2;
    const int m0 = 16 * w + rh;              // warp-private D rows m0, m0+8
    const int i0 = blockIdx.x * PTS;

    // aux staging
    for (int idx = t; idx < 384; idx += BLOCK)
        reinterpret_cast<float*>(sm + WC1_OFF)[idx] = Wc_1[idx];
    if (t < 128) reinterpret_cast<float*>(sm + BCOL_OFF)[t] = Wd2_3[t * 129];

    // encodings (thread t -> point row t)
    float vx = 0.f, vy = 0.f, vz = 0.f;
    if (t < PTS) {
        int i = i0 + t;
        float p0 = 0.f, p1 = 0.f, p2 = 0.f;
        if (i < N) {
            const float* xp = x + 6 * i;
            p0 = xp[0]; p1 = xp[1]; p2 = xp[2];
            vx = xp[3]; vy = xp[4]; vz = xp[5];
        }
#pragma unroll
        for (int d = 0; d < 3; d++) {
            float base = (d == 0) ? p0 : ((d == 1) ? p1 : p2);
#pragma unroll
            for (int f = 0; f < 10; f++) {
                float s, c;
                sincosf(base * (CUDART_PI_F * (float)(1 << f)), &s, &c);
                encStore(sm, t, d * 20 + 2 * f, s, c);
            }
        }
        encStore(sm, t, 60, 0.f, 0.f);
        encStore(sm, t, 62, 0.f, 0.f);
    }

    const uint32_t aofs = (uint32_t)m0 * SA + q * 4;   // A act read / epilogue store base
    const uint32_t eofs = (uint32_t)m0 * SE + q * 4;
    const float* wc1  = reinterpret_cast<const float*>(sm + WC1_OFF);
    const float* bcol = reinterpret_cast<const float*>(sm + BCOL_OFF);

    for (int l = 0; l < 8; l++) {
        __syncthreads();                      // prior layer done reading B (+enc for L8)
        // copy this layer's weights into smem (hi+lo), straight uint4 memcpy
        {
            const int n16 = c_n16[l];
            const uint4* shi = reinterpret_cast<const uint4*>(g_whi + c_loff[l]);
            const uint4* slo = reinterpret_cast<const uint4*>(g_wlo + c_loff[l]);
            uint4* dhi = reinterpret_cast<uint4*>(sm + BHI_OFF);
            uint4* dlo = reinterpret_cast<uint4*>(sm + BLO_OFF);
            for (int i = t; i < n16; i += BLOCK) { dhi[i] = shi[i]; dlo[i] = slo[i]; }
        }
        if (l == 4 && t < PTS) {              // enc_pos dead after L4 -> view encoding
#pragma unroll
            for (int d = 0; d < 3; d++) {
                float base = (d == 0) ? vx : ((d == 1) ? vy : vz);
#pragma unroll
                for (int f = 0; f < 4; f++) {
                    float s, c;
                    sincosf(base * (CUDART_PI_F * (float)(1 << f)), &s, &c);
                    encStore(sm, t, d * 8 + 2 * f, s, c);
                }
            }
            encStore(sm, t, 24, 0.f, 0.f);
            encStore(sm, t, 26, 0.f, 0.f);
            encStore(sm, t, 28, 0.f, 0.f);
            encStore(sm, t, 30, 0.f, 0.f);
        }
        __syncthreads();                      // B (and enc) visible

        const int sB = c_sB[l], sB8 = sB * 8;
        const int ek = c_encKt[l], tot = ek + c_actKt[l];
        const uint32_t bb0 = (uint32_t)rh * sB + q * 4;

        float d[16][4];
#pragma unroll
        for (int nt = 0; nt < 16; nt++) {
            d[nt][0] = 0.f; d[nt][1] = 0.f; d[nt][2] = 0.f; d[nt][3] = 0.f;
        }

        for (int kt = 0; kt < tot; kt++) {
            const char* ab;
            int st, dlo;
            if (kt < ek) { ab = sm + EHI_OFF + eofs + kt * 32; st = SE; dlo = ELO_DELTA; }
            else { ab = sm + AHI_OFF + aofs + (kt - ek) * 32; st = SA; dlo = ALO_DELTA; }
            uint32_t ah[4], al[4];
            ah[0] = *reinterpret_cast<const uint32_t*>(ab);
            ah[1] = *reinterpret_cast<const uint32_t*>(ab + 8 * st);
            ah[2] = *reinterpret_cast<const uint32_t*>(ab + 16);
            ah[3] = *reinterpret_cast<const uint32_t*>(ab + 8 * st + 16);
            al[0] = *reinterpret_cast<const uint32_t*>(ab + dlo);
            al[1] = *reinterpret_cast<const uint32_t*>(ab + dlo + 8 * st);
            al[2] = *reinterpret_cast<const uint32_t*>(ab + dlo + 16);
            al[3] = *reinterpret_cast<const uint32_t*>(ab + dlo + 8 * st + 16);

            const char* bb = sm + BHI_OFF + bb0 + kt * 32;
#pragma unroll
            for (int nt = 0; nt < 16; nt++) {
                const char* bp = bb + nt * sB8;
                uint32_t bh[2], bl[2];
                bh[0] = *reinterpret_cast<const uint32_t*>(bp);
                bh[1] = *reinterpret_cast<const uint32_t*>(bp + 16);
                bl[0] = *reinterpret_cast<const uint32_t*>(bp + BLO_DELTA);
                bl[1] = *reinterpret_cast<const uint32_t*>(bp + BLO_DELTA + 16);
                mma16816(d[nt], ah, bh);
                mma16816(d[nt], ah, bl);
                mma16816(d[nt], al, bh);
            }
        }

        // ---- epilogue (warp-private rows m0, m0+8) ----
        const bool relu = (l != 2 && l != 6);
        if (l == 6 && q == 0) {               // density = rotated col0 (linear)
            reinterpret_cast<float*>(sm + DENS_OFF)[m0]     = d[0][0];
            reinterpret_cast<float*>(sm + DENS_OFF)[m0 + 8] = d[0][2];
        }
        float b0 = 0.f, b1 = 0.f;
        float g00 = 0.f, g01 = 0.f, g02 = 0.f, g10 = 0.f, g11 = 0.f, g12 = 0.f;
#pragma unroll
        for (int nt = 0; nt < 16; nt++) {
            float f00 = d[nt][0], f01 = d[nt][1], f10 = d[nt][2], f11 = d[nt][3];
            if (relu) {
                f00 = fmaxf(f00, 0.f); f01 = fmaxf(f01, 0.f);
                f10 = fmaxf(f10, 0.f); f11 = fmaxf(f11, 0.f);
            }
            const int c = nt * 8 + 2 * q;
            if (l == 5) {                     // blending partial on relu'd L6 act
                b0 = fmaf(f00, bcol[c], fmaf(f01, bcol[c + 1], b0));
                b1 = fmaf(f10, bcol[c], fmaf(f11, bcol[c + 1], b1));
            }
            if (l == 7) {                     // rgb partials on relu'd L8 act
                g00 = fmaf(f00, wc1[c * 3 + 0], fmaf(f01, wc1[(c + 1) * 3 + 0], g00));
                g01 = fmaf(f00, wc1[c * 3 + 1], fmaf(f01, wc1[(c + 1) * 3 + 1], g01));
                g02 = fmaf(f00, wc1[c * 3 + 2], fmaf(f01, wc1[(c + 1) * 3 + 2], g02));
                g10 = fmaf(f10, wc1[c * 3 + 0], fmaf(f11, wc1[(c + 1) * 3 + 0], g10));
                g11 = fmaf(f10, wc1[c * 3 + 1], fmaf(f11, wc1[(c + 1) * 3 + 1], g11));
                g12 = fmaf(f10, wc1[c * 3 + 2], fmaf(f11, wc1[(c + 1) * 3 + 2], g12));
            } else {                          // store act hi/lo for next layer
                uint32_t lp0, hp0 = packSplitHi(f00, f01, lp0);
                uint32_t lp1, hp1 = packSplitHi(f10, f11, lp1);
                char* p = sm + AHI_OFF + aofs + nt * 16;
                *reinterpret_cast<uint32_t*>(p)                      = hp0;
                *reinterpret_cast<uint32_t*>(p + 8 * SA)             = hp1;
                *reinterpret_cast<uint32_t*>(p + ALO_DELTA)          = lp0;
                *reinterpret_cast<uint32_t*>(p + ALO_DELTA + 8 * SA) = lp1;
            }
        }
        if (l == 5) {
            b0 += __shfl_xor_sync(0xffffffffu, b0, 1);
            b0 += __shfl_xor_sync(0xffffffffu, b0, 2);
            b1 += __shfl_xor_sync(0xffffffffu, b1, 1);
            b1 += __shfl_xor_sync(0xffffffffu, b1, 2);
            if (q == 0) {
                reinterpret_cast<float*>(sm + PB_OFF)[m0]     = b0;
                reinterpret_cast<float*>(sm + PB_OFF)[m0 + 8] = b1;
            }
        }
        if (l == 7) {
            g00 += __shfl_xor_sync(0xffffffffu, g00, 1); g00 += __shfl_xor_sync(0xffffffffu, g00, 2);
            g01 += __shfl_xor_sync(0xffffffffu, g01, 1); g01 += __shfl_xor_sync(0xffffffffu, g01, 2);
            g02 += __shfl_xor_sync(0xffffffffu, g02, 1); g02 += __shfl_xor_sync(0xffffffffu, g02, 2);
            g10 += __shfl_xor_sync(0xffffffffu, g10, 1); g10 += __shfl_xor_sync(0xffffffffu, g10, 2);
            g11 += __shfl_xor_sync(0xffffffffu, g11, 1); g11 += __shfl_xor_sync(0xffffffffu, g11, 2);
            g12 += __shfl_xor_sync(0xffffffffu, g12, 1); g12 += __shfl_xor_sync(0xffffffffu, g12, 2);
            if (q == 0) {
                float* pr = reinterpret_cast<float*>(sm + PR_OFF);
                pr[m0 * 3 + 0] = g00; pr[m0 * 3 + 1] = g01; pr[m0 * 3 + 2] = g02;
                pr[(m0 + 8) * 3 + 0] = g10; pr[(m0 + 8) * 3 + 1] = g11; pr[(m0 + 8) * 3 + 2] = g12;
            }
        }
    }

    __syncthreads();
    if (t < PTS) {
        int i = i0 + t;
        if (i < N) {
            const float* pr = reinterpret_cast<const float*>(sm + PR_OFF);
            float braw = reinterpret_cast<const float*>(sm + PB_OFF)[t];
            float* o = out + 5 * i;
            o[0] = pr[t * 3 + 0];
            o[1] = pr[t * 3 + 1];
            o[2] = pr[t * 3 + 2];
            o[3] = reinterpret_cast<const float*>(sm + DENS_OFF)[t];
            o[4] = 1.f / (1.f + expf(-braw));
        }
    }
}

extern "C" void kernel_launch(void* const* d_in, const int* in_sizes, int n_in,
                              void* d_out, int out_size) {
    const float* x     = (const float*)d_in[0];
    const float* Wd1_0 = (const float*)d_in[1];
    const float* Wd1_1 = (const float*)d_in[2];
    const float* Wd1_2 = (const float*)d_in[3];
    const float* Wd2_0 = (const float*)d_in[4];
    const float* Wd2_1 = (const float*)d_in[5];
    const float* Wd2_2 = (const float*)d_in[6];
    const float* Wd2_3 = (const float*)d_in[7];
    const float* Wc_0  = (const float*)d_in[8];
    const float* Wc_1  = (const float*)d_in[9];
    float* out = (float*)d_out;

    int N = in_sizes[0] / 6;
    if (N <= 0) return;

    prepass_kernel<<<(143360 + 255) / 256, 256>>>(Wd1_0, Wd1_1, Wd1_2, Wd2_0,
                                                  Wd2_1, Wd2_2, Wd2_3, Wc_0);

    cudaFuncSetAttribute(nerf_mma_kernel,
                         cudaFuncAttributeMaxDynamicSharedMemorySize, SMEM_BYTES);
    int grid = (N + PTS - 1) / PTS;
    nerf_mma_kernel<<<grid, BLOCK, SMEM_BYTES>>>(x, Wd2_3, Wc_1, out, N);
}

// round 7
// speedup vs baseline: 3.5620x; 1.1642x over previous
#include <cuda_runtime.h>
#include <cuda_bf16.h>
#include <math_constants.h>
#include <cstdint>

#define BLOCK 256
#define PTS   128

// ---- smem byte offsets ----
#define AHI_OFF   0         // act hi  [128][136] bf16 (stride 272B) = 34816
#define ALO_OFF   34816     // act lo
#define EHI_OFF   69632     // enc hi  [128][72] bf16 (stride 144B) = 18432
#define ELO_OFF   88064     // enc lo
#define BHI_OFF   106496    // weight hi, max 200*128*2 = 51200B
#define BLO_OFF   157696    // weight lo
#define WC1_OFF   208896    // Wc_1 fp32 [128][3]
#define BCOL_OFF  210432    // Wd2_3 col0 fp32 [128]
#define DENS_OFF  210944    // density fp32 [128]
#define PB_OFF    211456    // blend raw fp32 [128]
#define PR_OFF    211968    // rgb fp32 [128][3]
#define SMEM_BYTES 213504

#define SA 272
#define SE 144
#define BLO_DELTA 51200
#define ALO_DELTA 34816
#define ELO_DELTA 18432

// epilogue flag bits
#define F_RELU  1
#define F_STORE 2
#define F_DENS  4
#define F_BLEND 8
#define F_RGB   16

// ---- pre-converted weights: Bt[j][k] row-major, padded, bf16 hi/lo ----
__device__ __nv_bfloat16 g_whi[143360];
__device__ __nv_bfloat16 g_wlo[143360];

__constant__ int c_loff[9] = {0, 9216, 26624, 44032, 69632, 87040, 104448, 121856, 143360};
__constant__ int c_kpad[8] = {72, 136, 136, 200, 136, 136, 136, 168};
__constant__ int c_n16[8]  = {1152, 2176, 2176, 3200, 2176, 2176, 2176, 2688};

__global__ void prepass_kernel(const float* __restrict__ Wd1_0, const float* __restrict__ Wd1_1,
                               const float* __restrict__ Wd1_2, const float* __restrict__ Wd2_0,
                               const float* __restrict__ Wd2_1, const float* __restrict__ Wd2_2,
                               const float* __restrict__ Wd2_3, const float* __restrict__ Wc_0) {
    int e = blockIdx.x * blockDim.x + threadIdx.x;
    if (e >= 143360) return;
    int l = 0;
    while (e >= c_loff[l + 1]) l++;
    int r = e - c_loff[l];
    int kp = c_kpad[l];
    int j = r / kp;
    int k = r % kp;
    float v = 0.f;
    switch (l) {
        case 0: if (k < 60) v = Wd1_0[k * 128 + j]; break;
        case 1: if (k < 128) v = Wd1_1[k * 128 + j]; break;
        case 2: if (k < 128) v = Wd1_2[k * 128 + j]; break;
        case 3: if (k < 60) v = Wd2_0[k * 128 + j];
                else if (k >= 64 && k < 192) v = Wd2_0[(k - 4) * 128 + j];
                break;
        case 4: if (k < 128) v = Wd2_1[k * 128 + j]; break;
        case 5: if (k < 128) v = Wd2_2[k * 128 + j]; break;
        case 6: if (k < 128) v = Wd2_3[k * 129 + (j + 1)]; break;  // rotated
        case 7: if (k < 24) v = Wc_0[k * 128 + j];
                else if (k >= 32 && k < 160) v = Wc_0[(k - 8) * 128 + j];
                break;
    }
    __nv_bfloat16 hi = __float2bfloat16(v);
    __nv_bfloat16 lo = __float2bfloat16(v - __bfloat162float(hi));
    g_whi[e] = hi;
    g_wlo[e] = lo;
}

// ---- helpers ----
__device__ __forceinline__ void mma16816(float* d, const uint32_t* a, const uint32_t* b) {
    asm volatile(
        "mma.sync.aligned.m16n8k16.row.col.f32.bf16.bf16.f32 "
        "{%0,%1,%2,%3}, {%4,%5,%6,%7}, {%8,%9}, {%0,%1,%2,%3};"
        : "+f"(d[0]), "+f"(d[1]), "+f"(d[2]), "+f"(d[3])
        : "r"(a[0]), "r"(a[1]), "r"(a[2]), "r"(a[3]), "r"(b[0]), "r"(b[1]));
}

__device__ __forceinline__ void ldsm4(uint32_t* r, uint32_t addr) {
    asm volatile("ldmatrix.sync.aligned.m8n8.x4.shared.b16 {%0,%1,%2,%3}, [%4];"
                 : "=r"(r[0]), "=r"(r[1]), "=r"(r[2]), "=r"(r[3]) : "r"(addr));
}

__device__ __forceinline__ void cpasync16(uint32_t dst, const void* src) {
    asm volatile("cp.async.cg.shared.global [%0], [%1], 16;" :: "r"(dst), "l"(src));
}
#define CP_COMMIT() asm volatile("cp.async.commit_group;")
#define CP_WAIT0()  asm volatile("cp.async.wait_group 0;" ::: "memory")

__device__ __forceinline__ uint32_t smem_u32(const void* p) {
    uint32_t a;
    asm("{ .reg .u64 t; cvta.to.shared.u64 t, %1; cvt.u32.u64 %0, t; }" : "=r"(a) : "l"(p));
    return a;
}

__device__ __forceinline__ uint32_t packSplitHi(float f0, float f1, uint32_t& lp) {
    __nv_bfloat16 h0 = __float2bfloat16(f0), h1 = __float2bfloat16(f1);
    __nv_bfloat16 l0 = __float2bfloat16(f0 - __bfloat162float(h0));
    __nv_bfloat16 l1 = __float2bfloat16(f1 - __bfloat162float(h1));
    lp = ((uint32_t)__bfloat16_as_ushort(l1) << 16) | __bfloat16_as_ushort(l0);
    return ((uint32_t)__bfloat16_as_ushort(h1) << 16) | __bfloat16_as_ushort(h0);
}

__device__ __forceinline__ void encStore(char* sm, int row, int col, float f0, float f1) {
    uint32_t lp, hp = packSplitHi(f0, f1, lp);
    *reinterpret_cast<uint32_t*>(sm + EHI_OFF + row * SE + col * 2) = hp;
    *reinterpret_cast<uint32_t*>(sm + ELO_OFF + row * SE + col * 2) = lp;
}

__device__ __forceinline__ void copyB_async(uint32_t sb, int l) {
    const int n16 = c_n16[l];
    const char* shi = reinterpret_cast<const char*>(g_whi + c_loff[l]);
    const char* slo = reinterpret_cast<const char*>(g_wlo + c_loff[l]);
    const uint32_t dhi = sb + BHI_OFF, dlo = sb + BLO_OFF;
    for (int i = threadIdx.x; i < n16; i += BLOCK) {
        cpasync16(dhi + i * 16, shi + i * 16);
        cpasync16(dlo + i * 16, slo + i * 16);
    }
    CP_COMMIT();
}

// One layer: EK enc k-tiles + AK act k-tiles, weight row stride SB bytes.
// Shared (__noinline__) across same-shape layers; runtime epilogue flags.
template<int EK, int AK, int SB>
__device__ __noinline__ void layerT(char* sm, uint32_t sb, int flags) {
    const int t = threadIdx.x;
    const int w = t >> 5, lane = t & 31;
    const int q = lane & 3, rh = lane >> 2;
    const int m0 = 16 * w + rh;
    const int arow = lane & 15, asel = lane >> 4;
    const int brow = (lane & 7) + ((lane >> 4) << 3);
    const int bsel = (lane >> 3) & 1;

    const uint32_t aHi = sb + AHI_OFF + (uint32_t)(16 * w + arow) * SA + asel * 16;
    const uint32_t aLo = aHi + ALO_DELTA;
    const uint32_t eHi = sb + EHI_OFF + (uint32_t)(16 * w + arow) * SE + asel * 16;
    const uint32_t eLo = eHi + ELO_DELTA;
    const uint32_t bHi0 = sb + BHI_OFF + (uint32_t)brow * SB + bsel * 16;

    float d[16][4];
#pragma unroll
    for (int nt = 0; nt < 16; nt++) {
        d[nt][0] = 0.f; d[nt][1] = 0.f; d[nt][2] = 0.f; d[nt][3] = 0.f;
    }

#pragma unroll
    for (int kt = 0; kt < EK + AK; kt++) {
        uint32_t ah[4], al[4];
        if (kt < EK) { ldsm4(ah, eHi + kt * 32); ldsm4(al, eLo + kt * 32); }
        else         { ldsm4(ah, aHi + (kt - EK) * 32); ldsm4(al, aLo + (kt - EK) * 32); }
#pragma unroll
        for (int n2 = 0; n2 < 8; n2++) {
            const uint32_t bp = bHi0 + kt * 32 + n2 * (16 * SB);
            uint32_t bh[4], bl[4];
            ldsm4(bh, bp);
            ldsm4(bl, bp + BLO_DELTA);
            mma16816(d[2 * n2],     ah, bh);
            mma16816(d[2 * n2],     ah, bl);
            mma16816(d[2 * n2],     al, bh);
            mma16816(d[2 * n2 + 1], ah, bh + 2);
            mma16816(d[2 * n2 + 1], ah, bl + 2);
            mma16816(d[2 * n2 + 1], al, bh + 2);
        }
    }

    // ---- epilogue (warp-private rows m0, m0+8) ----
    const bool relu  = flags & F_RELU;
    const bool store = flags & F_STORE;
    const float* wc1  = reinterpret_cast<const float*>(sm + WC1_OFF);
    const float* bcol = reinterpret_cast<const float*>(sm + BCOL_OFF);

    if ((flags & F_DENS) && q == 0) {
        reinterpret_cast<float*>(sm + DENS_OFF)[m0]     = d[0][0];
        reinterpret_cast<float*>(sm + DENS_OFF)[m0 + 8] = d[0][2];
    }
    float b0 = 0.f, b1 = 0.f;
    float g00 = 0.f, g01 = 0.f, g02 = 0.f, g10 = 0.f, g11 = 0.f, g12 = 0.f;
    const uint32_t aofs = (uint32_t)m0 * SA + q * 4;
#pragma unroll
    for (int nt = 0; nt < 16; nt++) {
        float f00 = d[nt][0], f01 = d[nt][1], f10 = d[nt][2], f11 = d[nt][3];
        if (relu) {
            f00 = fmaxf(f00, 0.f); f01 = fmaxf(f01, 0.f);
            f10 = fmaxf(f10, 0.f); f11 = fmaxf(f11, 0.f);
        }
        const int c = nt * 8 + 2 * q;
        if (flags & F_BLEND) {
            b0 = fmaf(f00, bcol[c], fmaf(f01, bcol[c + 1], b0));
            b1 = fmaf(f10, bcol[c], fmaf(f11, bcol[c + 1], b1));
        }
        if (flags & F_RGB) {
            g00 = fmaf(f00, wc1[c * 3 + 0], fmaf(f01, wc1[(c + 1) * 3 + 0], g00));
            g01 = fmaf(f00, wc1[c * 3 + 1], fmaf(f01, wc1[(c + 1) * 3 + 1], g01));
            g02 = fmaf(f00, wc1[c * 3 + 2], fmaf(f01, wc1[(c + 1) * 3 + 2], g02));
            g10 = fmaf(f10, wc1[c * 3 + 0], fmaf(f11, wc1[(c + 1) * 3 + 0], g10));
            g11 = fmaf(f10, wc1[c * 3 + 1], fmaf(f11, wc1[(c + 1) * 3 + 1], g11));
            g12 = fmaf(f10, wc1[c * 3 + 2], fmaf(f11, wc1[(c + 1) * 3 + 2], g12));
        }
        if (store) {
            uint32_t lp0, hp0 = packSplitHi(f00, f01, lp0);
            uint32_t lp1, hp1 = packSplitHi(f10, f11, lp1);
            char* p = sm + AHI_OFF + aofs + nt * 16;
            *reinterpret_cast<uint32_t*>(p)                      = hp0;
            *reinterpret_cast<uint32_t*>(p + 8 * SA)             = hp1;
            *reinterpret_cast<uint32_t*>(p + ALO_DELTA)          = lp0;
            *reinterpret_cast<uint32_t*>(p + ALO_DELTA + 8 * SA) = lp1;
        }
    }
    if (flags & F_BLEND) {
        b0 += __shfl_xor_sync(0xffffffffu, b0, 1);
        b0 += __shfl_xor_sync(0xffffffffu, b0, 2);
        b1 += __shfl_xor_sync(0xffffffffu, b1, 1);
        b1 += __shfl_xor_sync(0xffffffffu, b1, 2);
        if (q == 0) {
            reinterpret_cast<float*>(sm + PB_OFF)[m0]     = b0;
            reinterpret_cast<float*>(sm + PB_OFF)[m0 + 8] = b1;
        }
    }
    if (flags & F_RGB) {
        g00 += __shfl_xor_sync(0xffffffffu, g00, 1); g00 += __shfl_xor_sync(0xffffffffu, g00, 2);
        g01 += __shfl_xor_sync(0xffffffffu, g01, 1); g01 += __shfl_xor_sync(0xffffffffu, g01, 2);
        g02 += __shfl_xor_sync(0xffffffffu, g02, 1); g02 += __shfl_xor_sync(0xffffffffu, g02, 2);
        g10 += __shfl_xor_sync(0xffffffffu, g10, 1); g10 += __shfl_xor_sync(0xffffffffu, g10, 2);
        g11 += __shfl_xor_sync(0xffffffffu, g11, 1); g11 += __shfl_xor_sync(0xffffffffu, g11, 2);
        g12 += __shfl_xor_sync(0xffffffffu, g12, 1); g12 += __shfl_xor_sync(0xffffffffu, g12, 2);
        if (q == 0) {
            float* pr = reinterpret_cast<float*>(sm + PR_OFF);
            pr[m0 * 3 + 0] = g00; pr[m0 * 3 + 1] = g01; pr[m0 * 3 + 2] = g02;
            pr[(m0 + 8) * 3 + 0] = g10; pr[(m0 + 8) * 3 + 1] = g11; pr[(m0 + 8) * 3 + 2] = g12;
        }
    }
}

__global__ void __launch_bounds__(BLOCK, 1)
nerf_mma_kernel(const float* __restrict__ x, const float* __restrict__ Wd2_3,
                const float* __restrict__ Wc_1, float* __restrict__ out, int N) {
    extern __shared__ char sm[];
    const uint32_t sb = smem_u32(sm);
    const int t = threadIdx.x;
    const int i0 = blockIdx.x * PTS;

    // start layer-0 weight copy immediately (B unused yet)
    copyB_async(sb, 0);

    // aux staging
    for (int idx = t; idx < 384; idx += BLOCK)
        reinterpret_cast<float*>(sm + WC1_OFF)[idx] = Wc_1[idx];
    if (t < 128) reinterpret_cast<float*>(sm + BCOL_OFF)[t] = Wd2_3[t * 129];

    // positional encoding (thread t -> point row t); keep view dir in regs
    float vx = 0.f, vy = 0.f, vz = 0.f;
    if (t < PTS) {
        int i = i0 + t;
        float p0 = 0.f, p1 = 0.f, p2 = 0.f;
        if (i < N) {
            const float* xp = x + 6 * i;
            p0 = xp[0]; p1 = xp[1]; p2 = xp[2];
            vx = xp[3]; vy = xp[4]; vz = xp[5];
        }
#pragma unroll
        for (int dd = 0; dd < 3; dd++) {
            float base = (dd == 0) ? p0 : ((dd == 1) ? p1 : p2);
#pragma unroll
            for (int f = 0; f < 10; f++) {
                float s, c;
                sincosf(base * (CUDART_PI_F * (float)(1 << f)), &s, &c);
                encStore(sm, t, dd * 20 + 2 * f, s, c);
            }
        }
        encStore(sm, t, 60, 0.f, 0.f);
        encStore(sm, t, 62, 0.f, 0.f);
    }

    CP_WAIT0(); __syncthreads();
    layerT<4, 0, 144>(sm, sb, F_RELU | F_STORE);                 // L1

    __syncthreads(); copyB_async(sb, 1); CP_WAIT0(); __syncthreads();
    layerT<0, 8, 272>(sm, sb, F_RELU | F_STORE);                 // L2

    __syncthreads(); copyB_async(sb, 2); CP_WAIT0(); __syncthreads();
    layerT<0, 8, 272>(sm, sb, F_STORE);                          // L3 (linear)

    __syncthreads(); copyB_async(sb, 3); CP_WAIT0(); __syncthreads();
    layerT<4, 8, 400>(sm, sb, F_RELU | F_STORE);                 // L4

    __syncthreads(); copyB_async(sb, 4);
    if (t < PTS) {                     // enc_pos dead -> view encoding
#pragma unroll
        for (int dd = 0; dd < 3; dd++) {
            float base = (dd == 0) ? vx : ((dd == 1) ? vy : vz);
#pragma unroll
            for (int f = 0; f < 4; f++) {
                float s, c;
                sincosf(base * (CUDART_PI_F * (float)(1 << f)), &s, &c);
                encStore(sm, t, dd * 8 + 2 * f, s, c);
            }
        }
        encStore(sm, t, 24, 0.f, 0.f);
        encStore(sm, t, 26, 0.f, 0.f);
        encStore(sm, t, 28, 0.f, 0.f);
        encStore(sm, t, 30, 0.f, 0.f);
    }
    CP_WAIT0(); __syncthreads();
    layerT<0, 8, 272>(sm, sb, F_RELU | F_STORE);                 // L5

    __syncthreads(); copyB_async(sb, 5); CP_WAIT0(); __syncthreads();
    layerT<0, 8, 272>(sm, sb, F_RELU | F_STORE | F_BLEND);       // L6

    __syncthreads(); copyB_async(sb, 6); CP_WAIT0(); __syncthreads();
    layerT<0, 8, 272>(sm, sb, F_STORE | F_DENS);                 // L7 (linear)

    __syncthreads(); copyB_async(sb, 7); CP_WAIT0(); __syncthreads();
    layerT<2, 8, 336>(sm, sb, F_RELU | F_RGB);                   // L8

    __syncthreads();
    if (t < PTS) {
        int i = i0 + t;
        if (i < N) {
            const float* pr = reinterpret_cast<const float*>(sm + PR_OFF);
            float braw = reinterpret_cast<const float*>(sm + PB_OFF)[t];
            float* o = out + 5 * i;
            o[0] = pr[t * 3 + 0];
            o[1] = pr[t * 3 + 1];
            o[2] = pr[t * 3 + 2];
            o[3] = reinterpret_cast<const float*>(sm + DENS_OFF)[t];
            o[4] = 1.f / (1.f + expf(-braw));
        }
    }
}

extern "C" void kernel_launch(void* const* d_in, const int* in_sizes, int n_in,
                              void* d_out, int out_size) {
    const float* x     = (const float*)d_in[0];
    const float* Wd1_0 = (const float*)d_in[1];
    const float* Wd1_1 = (const float*)d_in[2];
    const float* Wd1_2 = (const float*)d_in[3];
    const float* Wd2_0 = (const float*)d_in[4];
    const float* Wd2_1 = (const float*)d_in[5];
    const float* Wd2_2 = (const float*)d_in[6];
    const float* Wd2_3 = (const float*)d_in[7];
    const float* Wc_0  = (const float*)d_in[8];
    const float* Wc_1  = (const float*)d_in[9];
    float* out = (float*)d_out;

    int N = in_sizes[0] / 6;
    if (N <= 0) return;

    prepass_kernel<<<(143360 + 255) / 256, 256>>>(Wd1_0, Wd1_1, Wd1_2, Wd2_0,
                                                  Wd2_1, Wd2_2, Wd2_3, Wc_0);

    cudaFuncSetAttribute(nerf_mma_kernel,
                         cudaFuncAttributeMaxDynamicSharedMemorySize, SMEM_BYTES);
    int grid = (N + PTS - 1) / PTS;
    nerf_mma_kernel<<<grid, BLOCK, SMEM_BYTES>>>(x, Wd2_3, Wc_1, out, N);
}

// round 9
// speedup vs baseline: 3.8446x; 1.0793x over previous
#include <cuda_runtime.h>
#include <cuda_bf16.h>
#include <math_constants.h>
#include <cstdint>

#define BLOCK 512
#define PTS   128

// ---- smem byte offsets ----
#define AHI_OFF   0         // act hi  [128][136] bf16 (stride 272B) = 34816
#define ALO_OFF   34816     // act lo
#define EHI_OFF   69632     // enc hi  [128][72] bf16 (stride 144B) = 18432
#define ELO_OFF   88064     // enc lo
#define BHI_OFF   106496    // weight hi, max 200*128*2 = 51200B
#define BLO_OFF   157696    // weight lo
#define WC1_OFF   208896    // Wc_1 fp32 [128][3]
#define BCOL_OFF  210432    // Wd2_3 col0 fp32 [128]
#define DENS_OFF  210944    // density fp32 [128]
#define PB_OFF    211456    // blend partials fp32 [2][128]
#define PR_OFF    212480    // rgb partials fp32 [2][128][3]
#define SMEM_BYTES 215552

#define SA 272
#define SE 144
#define BLO_DELTA 51200
#define ALO_DELTA 34816
#define ELO_DELTA 18432

// epilogue flag bits
#define F_RELU  1
#define F_STORE 2
#define F_DENS  4
#define F_BLEND 8
#define F_RGB   16

// ---- pre-converted weights: Bt[j][k] row-major, padded, bf16 hi/lo ----
__device__ __nv_bfloat16 g_whi[143360];
__device__ __nv_bfloat16 g_wlo[143360];

__constant__ int c_loff[9] = {0, 9216, 26624, 44032, 69632, 87040, 104448, 121856, 143360};
__constant__ int c_kpad[8] = {72, 136, 136, 200, 136, 136, 136, 168};
__constant__ int c_n16[8]  = {1152, 2176, 2176, 3200, 2176, 2176, 2176, 2688};

__global__ void prepass_kernel(const float* __restrict__ Wd1_0, const float* __restrict__ Wd1_1,
                               const float* __restrict__ Wd1_2, const float* __restrict__ Wd2_0,
                               const float* __restrict__ Wd2_1, const float* __restrict__ Wd2_2,
                               const float* __restrict__ Wd2_3, const float* __restrict__ Wc_0) {
    int e = blockIdx.x * blockDim.x + threadIdx.x;
    if (e >= 143360) return;
    int l = 0;
    while (e >= c_loff[l + 1]) l++;
    int r = e - c_loff[l];
    int kp = c_kpad[l];
    int j = r / kp;
    int k = r % kp;
    float v = 0.f;
    switch (l) {
        case 0: if (k < 60) v = Wd1_0[k * 128 + j]; break;
        case 1: if (k < 128) v = Wd1_1[k * 128 + j]; break;
        case 2: if (k < 128) v = Wd1_2[k * 128 + j]; break;
        case 3: if (k < 60) v = Wd2_0[k * 128 + j];
                else if (k >= 64 && k < 192) v = Wd2_0[(k - 4) * 128 + j];
                break;
        case 4: if (k < 128) v = Wd2_1[k * 128 + j]; break;
        case 5: if (k < 128) v = Wd2_2[k * 128 + j]; break;
        case 6: if (k < 128) v = Wd2_3[k * 129 + (j + 1)]; break;  // rotated
        case 7: if (k < 24) v = Wc_0[k * 128 + j];
                else if (k >= 32 && k < 160) v = Wc_0[(k - 8) * 128 + j];
                break;
    }
    __nv_bfloat16 hi = __float2bfloat16(v);
    __nv_bfloat16 lo = __float2bfloat16(v - __bfloat162float(hi));
    g_whi[e] = hi;
    g_wlo[e] = lo;
}

// ---- helpers ----
__device__ __forceinline__ void mma16816(float* d, const uint32_t* a, const uint32_t* b) {
    asm volatile(
        "mma.sync.aligned.m16n8k16.row.col.f32.bf16.bf16.f32 "
        "{%0,%1,%2,%3}, {%4,%5,%6,%7}, {%8,%9}, {%0,%1,%2,%3};"
        : "+f"(d[0]), "+f"(d[1]), "+f"(d[2]), "+f"(d[3])
        : "r"(a[0]), "r"(a[1]), "r"(a[2]), "r"(a[3]), "r"(b[0]), "r"(b[1]));
}

__device__ __forceinline__ void ldsm4(uint32_t* r, uint32_t addr) {
    asm volatile("ldmatrix.sync.aligned.m8n8.x4.shared.b16 {%0,%1,%2,%3}, [%4];"
                 : "=r"(r[0]), "=r"(r[1]), "=r"(r[2]), "=r"(r[3]) : "r"(addr));
}

__device__ __forceinline__ void cpasync16(uint32_t dst, const void* src) {
    asm volatile("cp.async.cg.shared.global [%0], [%1], 16;" :: "r"(dst), "l"(src));
}
#define CP_COMMIT() asm volatile("cp.async.commit_group;")
#define CP_WAIT0()  asm volatile("cp.async.wait_group 0;" ::: "memory")

__device__ __forceinline__ uint32_t smem_u32(const void* p) {
    uint32_t a;
    asm("{ .reg .u64 t; cvta.to.shared.u64 t, %1; cvt.u32.u64 %0, t; }" : "=r"(a) : "l"(p));
    return a;
}

__device__ __forceinline__ uint32_t packSplitHi(float f0, float f1, uint32_t& lp) {
    __nv_bfloat16 h0 = __float2bfloat16(f0), h1 = __float2bfloat16(f1);
    __nv_bfloat16 l0 = __float2bfloat16(f0 - __bfloat162float(h0));
    __nv_bfloat16 l1 = __float2bfloat16(f1 - __bfloat162float(h1));
    lp = ((uint32_t)__bfloat16_as_ushort(l1) << 16) | __bfloat16_as_ushort(l0);
    return ((uint32_t)__bfloat16_as_ushort(h1) << 16) | __bfloat16_as_ushort(h0);
}

__device__ __forceinline__ void encStore(char* sm, int row, int col, float f0, float f1) {
    uint32_t lp, hp = packSplitHi(f0, f1, lp);
    *reinterpret_cast<uint32_t*>(sm + EHI_OFF + row * SE + col * 2) = hp;
    *reinterpret_cast<uint32_t*>(sm + ELO_OFF + row * SE + col * 2) = lp;
}

__device__ __forceinline__ void copyB_async(uint32_t sb, int l) {
    const int n16 = c_n16[l];
    const char* shi = reinterpret_cast<const char*>(g_whi + c_loff[l]);
    const char* slo = reinterpret_cast<const char*>(g_wlo + c_loff[l]);
    const uint32_t dhi = sb + BHI_OFF, dlo = sb + BLO_OFF;
    for (int i = threadIdx.x; i < n16; i += BLOCK) {
        cpasync16(dhi + i * 16, shi + i * 16);
        cpasync16(dlo + i * 16, slo + i * 16);
    }
    CP_COMMIT();
}

// One layer: EK enc k-tiles + AK act k-tiles, weight row stride SB bytes.
// 16 warps: warp = (m-group wm = w&7, N-half wg = w>>3). Warp tile: 16 rows x 64 cols.
// NOTE: act rows are read by BOTH wg-siblings of a wm-group, so a block-wide
// barrier separates the mainloop (reads) from the store epilogue (writes).
template<int EK, int AK, int SB>
__device__ __noinline__ void layerT(char* sm, uint32_t sb, int flags) {
    const int t = threadIdx.x;
    const int w = t >> 5, lane = t & 31;
    const int wm = w & 7, wg = w >> 3;
    const int q = lane & 3, rh = lane >> 2;
    const int m0 = 16 * wm + rh;
    const int arow = lane & 15, asel = lane >> 4;
    const int brow = (lane & 7) + ((lane >> 4) << 3);
    const int bsel = (lane >> 3) & 1;

    const uint32_t aHi = sb + AHI_OFF + (uint32_t)(16 * wm + arow) * SA + asel * 16;
    const uint32_t aLo = aHi + ALO_DELTA;
    const uint32_t eHi = sb + EHI_OFF + (uint32_t)(16 * wm + arow) * SE + asel * 16;
    const uint32_t eLo = eHi + ELO_DELTA;
    const uint32_t bHi0 = sb + BHI_OFF + (uint32_t)(brow + wg * 64) * SB + bsel * 16;

    float d[8][4];
#pragma unroll
    for (int nt = 0; nt < 8; nt++) {
        d[nt][0] = 0.f; d[nt][1] = 0.f; d[nt][2] = 0.f; d[nt][3] = 0.f;
    }

#pragma unroll
    for (int kt = 0; kt < EK + AK; kt++) {
        uint32_t ah[4], al[4];
        if (kt < EK) { ldsm4(ah, eHi + kt * 32); ldsm4(al, eLo + kt * 32); }
        else         { ldsm4(ah, aHi + (kt - EK) * 32); ldsm4(al, aLo + (kt - EK) * 32); }
#pragma unroll
        for (int n2 = 0; n2 < 4; n2++) {
            const uint32_t bp = bHi0 + kt * 32 + n2 * (16 * SB);
            uint32_t bh[4], bl[4];
            ldsm4(bh, bp);
            ldsm4(bl, bp + BLO_DELTA);
            mma16816(d[2 * n2],     ah, bh);
            mma16816(d[2 * n2],     ah, bl);
            mma16816(d[2 * n2],     al, bh);
            mma16816(d[2 * n2 + 1], ah, bh + 2);
            mma16816(d[2 * n2 + 1], ah, bl + 2);
            mma16816(d[2 * n2 + 1], al, bh + 2);
        }
    }

    // RACE FIX (R8): wg-sibling warps read the same act rows this warp writes.
    // All mainloop reads must complete block-wide before any epilogue store.
    __syncthreads();

    // ---- epilogue (rows m0, m0+8; cols wg*64 .. wg*64+63) ----
    const bool relu  = flags & F_RELU;
    const bool store = flags & F_STORE;
    const float* wc1  = reinterpret_cast<const float*>(sm + WC1_OFF);
    const float* bcol = reinterpret_cast<const float*>(sm + BCOL_OFF);

    if ((flags & F_DENS) && wg == 0 && q == 0) {   // logical col 0 = density
        reinterpret_cast<float*>(sm + DENS_OFF)[m0]     = d[0][0];
        reinterpret_cast<float*>(sm + DENS_OFF)[m0 + 8] = d[0][2];
    }
    float b0 = 0.f, b1 = 0.f;
    float g00 = 0.f, g01 = 0.f, g02 = 0.f, g10 = 0.f, g11 = 0.f, g12 = 0.f;
    const uint32_t aofs = (uint32_t)m0 * SA + q * 4 + wg * 128;
#pragma unroll
    for (int nt = 0; nt < 8; nt++) {
        float f00 = d[nt][0], f01 = d[nt][1], f10 = d[nt][2], f11 = d[nt][3];
        if (relu) {
            f00 = fmaxf(f00, 0.f); f01 = fmaxf(f01, 0.f);
            f10 = fmaxf(f10, 0.f); f11 = fmaxf(f11, 0.f);
        }
        const int c = wg * 64 + nt * 8 + 2 * q;
        if (flags & F_BLEND) {
            b0 = fmaf(f00, bcol[c], fmaf(f01, bcol[c + 1], b0));
            b1 = fmaf(f10, bcol[c], fmaf(f11, bcol[c + 1], b1));
        }
        if (flags & F_RGB) {
            g00 = fmaf(f00, wc1[c * 3 + 0], fmaf(f01, wc1[(c + 1) * 3 + 0], g00));
            g01 = fmaf(f00, wc1[c * 3 + 1], fmaf(f01, wc1[(c + 1) * 3 + 1], g01));
            g02 = fmaf(f00, wc1[c * 3 + 2], fmaf(f01, wc1[(c + 1) * 3 + 2], g02));
            g10 = fmaf(f10, wc1[c * 3 + 0], fmaf(f11, wc1[(c + 1) * 3 + 0], g10));
            g11 = fmaf(f10, wc1[c * 3 + 1], fmaf(f11, wc1[(c + 1) * 3 + 1], g11));
            g12 = fmaf(f10, wc1[c * 3 + 2], fmaf(f11, wc1[(c + 1) * 3 + 2], g12));
        }
        if (store) {
            uint32_t lp0, hp0 = packSplitHi(f00, f01, lp0);
            uint32_t lp1, hp1 = packSplitHi(f10, f11, lp1);
            char* p = sm + AHI_OFF + aofs + nt * 16;
            *reinterpret_cast<uint32_t*>(p)                      = hp0;
            *reinterpret_cast<uint32_t*>(p + 8 * SA)             = hp1;
            *reinterpret_cast<uint32_t*>(p + ALO_DELTA)          = lp0;
            *reinterpret_cast<uint32_t*>(p + ALO_DELTA + 8 * SA) = lp1;
        }
    }
    if (flags & F_BLEND) {
        b0 += __shfl_xor_sync(0xffffffffu, b0, 1);
        b0 += __shfl_xor_sync(0xffffffffu, b0, 2);
        b1 += __shfl_xor_sync(0xffffffffu, b1, 1);
        b1 += __shfl_xor_sync(0xffffffffu, b1, 2);
        if (q == 0) {
            reinterpret_cast<float*>(sm + PB_OFF)[wg * 128 + m0]     = b0;
            reinterpret_cast<float*>(sm + PB_OFF)[wg * 128 + m0 + 8] = b1;
        }
    }
    if (flags & F_RGB) {
        g00 += __shfl_xor_sync(0xffffffffu, g00, 1); g00 += __shfl_xor_sync(0xffffffffu, g00, 2);
        g01 += __shfl_xor_sync(0xffffffffu, g01, 1); g01 += __shfl_xor_sync(0xffffffffu, g01, 2);
        g02 += __shfl_xor_sync(0xffffffffu, g02, 1); g02 += __shfl_xor_sync(0xffffffffu, g02, 2);
        g10 += __shfl_xor_sync(0xffffffffu, g10, 1); g10 += __shfl_xor_sync(0xffffffffu, g10, 2);
        g11 += __shfl_xor_sync(0xffffffffu, g11, 1); g11 += __shfl_xor_sync(0xffffffffu, g11, 2);
        g12 += __shfl_xor_sync(0xffffffffu, g12, 1); g12 += __shfl_xor_sync(0xffffffffu, g12, 2);
        if (q == 0) {
            float* pr = reinterpret_cast<float*>(sm + PR_OFF) + (wg * 128) * 3;
            pr[m0 * 3 + 0] = g00; pr[m0 * 3 + 1] = g01; pr[m0 * 3 + 2] = g02;
            pr[(m0 + 8) * 3 + 0] = g10; pr[(m0 + 8) * 3 + 1] = g11; pr[(m0 + 8) * 3 + 2] = g12;
        }
    }
}

__global__ void __launch_bounds__(BLOCK, 1)
nerf_mma_kernel(const float* __restrict__ x, const float* __restrict__ Wd2_3,
                const float* __restrict__ Wc_1, float* __restrict__ out, int N) {
    extern __shared__ char sm[];
    const uint32_t sb = smem_u32(sm);
    const int t = threadIdx.x;
    const int i0 = blockIdx.x * PTS;

    // start layer-0 weight copy immediately
    copyB_async(sb, 0);

    // aux staging
    for (int idx = t; idx < 384; idx += BLOCK)
        reinterpret_cast<float*>(sm + WC1_OFF)[idx] = Wc_1[idx];
    if (t < 128) reinterpret_cast<float*>(sm + BCOL_OFF)[t] = Wd2_3[t * 129];

    // positional encoding (threads 0..127, one point each); view dir in regs
    float vx = 0.f, vy = 0.f, vz = 0.f;
    if (t < PTS) {
        int i = i0 + t;
        float p0 = 0.f, p1 = 0.f, p2 = 0.f;
        if (i < N) {
            const float* xp = x + 6 * i;
            p0 = xp[0]; p1 = xp[1]; p2 = xp[2];
            vx = xp[3]; vy = xp[4]; vz = xp[5];
        }
#pragma unroll
        for (int dd = 0; dd < 3; dd++) {
            float base = (dd == 0) ? p0 : ((dd == 1) ? p1 : p2);
#pragma unroll
            for (int f = 0; f < 10; f++) {
                float s, c;
                sincosf(base * (CUDART_PI_F * (float)(1 << f)), &s, &c);
                encStore(sm, t, dd * 20 + 2 * f, s, c);
            }
        }
        encStore(sm, t, 60, 0.f, 0.f);
        encStore(sm, t, 62, 0.f, 0.f);
    }

    CP_WAIT0(); __syncthreads();
    layerT<4, 0, 144>(sm, sb, F_RELU | F_STORE);                 // L1

    __syncthreads(); copyB_async(sb, 1); CP_WAIT0(); __syncthreads();
    layerT<0, 8, 272>(sm, sb, F_RELU | F_STORE);                 // L2

    __syncthreads(); copyB_async(sb, 2); CP_WAIT0(); __syncthreads();
    layerT<0, 8, 272>(sm, sb, F_STORE);                          // L3 (linear)

    __syncthreads(); copyB_async(sb, 3); CP_WAIT0(); __syncthreads();
    layerT<4, 8, 400>(sm, sb, F_RELU | F_STORE);                 // L4

    __syncthreads(); copyB_async(sb, 4);
    if (t < PTS) {                     // enc_pos dead -> view encoding
#pragma unroll
        for (int dd = 0; dd < 3; dd++) {
            float base = (dd == 0) ? vx : ((dd == 1) ? vy : vz);
#pragma unroll
            for (int f = 0; f < 4; f++) {
                float s, c;
                sincosf(base * (CUDART_PI_F * (float)(1 << f)), &s, &c);
                encStore(sm, t, dd * 8 + 2 * f, s, c);
            }
        }
        encStore(sm, t, 24, 0.f, 0.f);
        encStore(sm, t, 26, 0.f, 0.f);
        encStore(sm, t, 28, 0.f, 0.f);
        encStore(sm, t, 30, 0.f, 0.f);
    }
    CP_WAIT0(); __syncthreads();
    layerT<0, 8, 272>(sm, sb, F_RELU | F_STORE);                 // L5

    __syncthreads(); copyB_async(sb, 5); CP_WAIT0(); __syncthreads();
    layerT<0, 8, 272>(sm, sb, F_RELU | F_STORE | F_BLEND);       // L6

    __syncthreads(); copyB_async(sb, 6); CP_WAIT0(); __syncthreads();
    layerT<0, 8, 272>(sm, sb, F_STORE | F_DENS);                 // L7 (linear)

    __syncthreads(); copyB_async(sb, 7); CP_WAIT0(); __syncthreads();
    layerT<2, 8, 336>(sm, sb, F_RELU | F_RGB);                   // L8

    __syncthreads();
    if (t < PTS) {
        int i = i0 + t;
        if (i < N) {
            const float* pr = reinterpret_cast<const float*>(sm + PR_OFF);
            const float* pb = reinterpret_cast<const float*>(sm + PB_OFF);
            float braw = pb[t] + pb[128 + t];
            float* o = out + 5 * i;
            o[0] = pr[t * 3 + 0] + pr[(128 + t) * 3 + 0];
            o[1] = pr[t * 3 + 1] + pr[(128 + t) * 3 + 1];
            o[2] = pr[t * 3 + 2] + pr[(128 + t) * 3 + 2];
            o[3] = reinterpret_cast<const float*>(sm + DENS_OFF)[t];
            o[4] = 1.f / (1.f + expf(-braw));
        }
    }
}

extern "C" void kernel_launch(void* const* d_in, const int* in_sizes, int n_in,
                              void* d_out, int out_size) {
    const float* x     = (const float*)d_in[0];
    const float* Wd1_0 = (const float*)d_in[1];
    const float* Wd1_1 = (const float*)d_in[2];
    const float* Wd1_2 = (const float*)d_in[3];
    const float* Wd2_0 = (const float*)d_in[4];
    const float* Wd2_1 = (const float*)d_in[5];
    const float* Wd2_2 = (const float*)d_in[6];
    const float* Wd2_3 = (const float*)d_in[7];
    const float* Wc_0  = (const float*)d_in[8];
    const float* Wc_1  = (const float*)d_in[9];
    float* out = (float*)d_out;

    int N = in_sizes[0] / 6;
    if (N <= 0) return;

    prepass_kernel<<<(143360 + 255) / 256, 256>>>(Wd1_0, Wd1_1, Wd1_2, Wd2_0,
                                                  Wd2_1, Wd2_2, Wd2_3, Wc_0);

    cudaFuncSetAttribute(nerf_mma_kernel,
                         cudaFuncAttributeMaxDynamicSharedMemorySize, SMEM_BYTES);
    int grid = (N + PTS - 1) / PTS;
    nerf_mma_kernel<<<grid, BLOCK, SMEM_BYTES>>>(x, Wd2_3, Wc_1, out, N);
}

// round 10
// speedup vs baseline: 3.9234x; 1.0205x over previous
#include <cuda_runtime.h>
#include <cuda_bf16.h>
#include <math_constants.h>
#include <cstdint>

#define BLOCK 512
#define PTS   128

// ---- smem byte offsets ----
#define AHI_OFF   0         // act hi  [128][136] bf16 (stride 272B) = 34816
#define ALO_OFF   34816     // act lo
#define EHI_OFF   69632     // enc hi  [128][72] bf16 (stride 144B) = 18432
#define ELO_OFF   88064     // enc lo
#define BHI_OFF   106496    // weight hi, max 200*128*2 = 51200B
#define BLO_OFF   157696    // weight lo
#define WC1_OFF   208896    // Wc_1 fp32 [128][3]
#define BCOL_OFF  210432    // Wd2_3 col0 fp32 [128]
#define DENS_OFF  210944    // density fp32 [128]
#define PB_OFF    211456    // blend partials fp32 [4][128]
#define PR_OFF    213504    // rgb partials fp32 [4][128][3]
#define SMEM_BYTES 219648

#define SA 272
#define SE 144
#define BLO_DELTA 51200
#define ALO_DELTA 34816
#define ELO_DELTA 18432

// epilogue flag bits
#define F_RELU  1
#define F_STORE 2
#define F_DENS  4
#define F_BLEND 8
#define F_RGB   16

// ---- pre-converted weights: Bt[j][k] row-major, padded, bf16 hi/lo ----
__device__ __nv_bfloat16 g_whi[143360];
__device__ __nv_bfloat16 g_wlo[143360];

__constant__ int c_loff[9] = {0, 9216, 26624, 44032, 69632, 87040, 104448, 121856, 143360};
__constant__ int c_kpad[8] = {72, 136, 136, 200, 136, 136, 136, 168};
__constant__ int c_n16[8]  = {1152, 2176, 2176, 3200, 2176, 2176, 2176, 2688};

__global__ void prepass_kernel(const float* __restrict__ Wd1_0, const float* __restrict__ Wd1_1,
                               const float* __restrict__ Wd1_2, const float* __restrict__ Wd2_0,
                               const float* __restrict__ Wd2_1, const float* __restrict__ Wd2_2,
                               const float* __restrict__ Wd2_3, const float* __restrict__ Wc_0) {
    int e = blockIdx.x * blockDim.x + threadIdx.x;
    if (e >= 143360) return;
    int l = 0;
    while (e >= c_loff[l + 1]) l++;
    int r = e - c_loff[l];
    int kp = c_kpad[l];
    int j = r / kp;
    int k = r % kp;
    float v = 0.f;
    switch (l) {
        case 0: if (k < 60) v = Wd1_0[k * 128 + j]; break;
        case 1: if (k < 128) v = Wd1_1[k * 128 + j]; break;
        case 2: if (k < 128) v = Wd1_2[k * 128 + j]; break;
        case 3: if (k < 60) v = Wd2_0[k * 128 + j];
                else if (k >= 64 && k < 192) v = Wd2_0[(k - 4) * 128 + j];
                break;
        case 4: if (k < 128) v = Wd2_1[k * 128 + j]; break;
        case 5: if (k < 128) v = Wd2_2[k * 128 + j]; break;
        case 6: if (k < 128) v = Wd2_3[k * 129 + (j + 1)]; break;  // rotated
        case 7: if (k < 24) v = Wc_0[k * 128 + j];
                else if (k >= 32 && k < 160) v = Wc_0[(k - 8) * 128 + j];
                break;
    }
    __nv_bfloat16 hi = __float2bfloat16(v);
    __nv_bfloat16 lo = __float2bfloat16(v - __bfloat162float(hi));
    g_whi[e] = hi;
    g_wlo[e] = lo;
}

// ---- helpers ----
__device__ __forceinline__ void mma16816(float* d, const uint32_t* a, const uint32_t* b) {
    asm volatile(
        "mma.sync.aligned.m16n8k16.row.col.f32.bf16.bf16.f32 "
        "{%0,%1,%2,%3}, {%4,%5,%6,%7}, {%8,%9}, {%0,%1,%2,%3};"
        : "+f"(d[0]), "+f"(d[1]), "+f"(d[2]), "+f"(d[3])
        : "r"(a[0]), "r"(a[1]), "r"(a[2]), "r"(a[3]), "r"(b[0]), "r"(b[1]));
}

__device__ __forceinline__ void ldsm4(uint32_t* r, uint32_t addr) {
    asm volatile("ldmatrix.sync.aligned.m8n8.x4.shared.b16 {%0,%1,%2,%3}, [%4];"
                 : "=r"(r[0]), "=r"(r[1]), "=r"(r[2]), "=r"(r[3]) : "r"(addr));
}

__device__ __forceinline__ void cpasync16(uint32_t dst, const void* src) {
    asm volatile("cp.async.cg.shared.global [%0], [%1], 16;" :: "r"(dst), "l"(src));
}
#define CP_COMMIT() asm volatile("cp.async.commit_group;")
#define CP_WAIT0()  asm volatile("cp.async.wait_group 0;" ::: "memory")

__device__ __forceinline__ uint32_t smem_u32(const void* p) {
    uint32_t a;
    asm("{ .reg .u64 t; cvta.to.shared.u64 t, %1; cvt.u32.u64 %0, t; }" : "=r"(a) : "l"(p));
    return a;
}

__device__ __forceinline__ uint32_t packSplitHi(float f0, float f1, uint32_t& lp) {
    __nv_bfloat16 h0 = __float2bfloat16(f0), h1 = __float2bfloat16(f1);
    __nv_bfloat16 l0 = __float2bfloat16(f0 - __bfloat162float(h0));
    __nv_bfloat16 l1 = __float2bfloat16(f1 - __bfloat162float(h1));
    lp = ((uint32_t)__bfloat16_as_ushort(l1) << 16) | __bfloat16_as_ushort(l0);
    return ((uint32_t)__bfloat16_as_ushort(h1) << 16) | __bfloat16_as_ushort(h0);
}

__device__ __forceinline__ void encStore(char* sm, int row, int col, float f0, float f1) {
    uint32_t lp, hp = packSplitHi(f0, f1, lp);
    *reinterpret_cast<uint32_t*>(sm + EHI_OFF + row * SE + col * 2) = hp;
    *reinterpret_cast<uint32_t*>(sm + ELO_OFF + row * SE + col * 2) = lp;
}

__device__ __forceinline__ void copyB_async(uint32_t sb, int l) {
    const int n16 = c_n16[l];
    const char* shi = reinterpret_cast<const char*>(g_whi + c_loff[l]);
    const char* slo = reinterpret_cast<const char*>(g_wlo + c_loff[l]);
    const uint32_t dhi = sb + BHI_OFF, dlo = sb + BLO_OFF;
    for (int i = threadIdx.x; i < n16; i += BLOCK) {
        cpasync16(dhi + i * 16, shi + i * 16);
        cpasync16(dlo + i * 16, slo + i * 16);
    }
    CP_COMMIT();
}

// One layer: EK enc k-tiles + AK act k-tiles, weight row stride SB bytes.
// 16 warps, warp tile 32 rows x 32 cols: wm = w&3 (rows 32wm..+31), wg = w>>2
// (cols 32wg..+31). After the race barrier, next layer's weight copy is issued
// (B reads done) so it overlaps the epilogue.
template<int EK, int AK, int SB>
__device__ __noinline__ void layerT(char* sm, uint32_t sb, int flags, int nextL) {
    const int t = threadIdx.x;
    const int w = t >> 5, lane = t & 31;
    const int wm = w & 3, wg = w >> 2;
    const int q = lane & 3, rh = lane >> 2;
    const int arow = lane & 15, asel = lane >> 4;
    const int brow = (lane & 7) + ((lane >> 4) << 3);
    const int bsel = (lane >> 3) & 1;

    const uint32_t aHi = sb + AHI_OFF + (uint32_t)(32 * wm + arow) * SA + asel * 16;
    const uint32_t eHi = sb + EHI_OFF + (uint32_t)(32 * wm + arow) * SE + asel * 16;
    const uint32_t bHi0 = sb + BHI_OFF + (uint32_t)(brow + wg * 32) * SB + bsel * 16;

    float d[2][4][4];
#pragma unroll
    for (int mt = 0; mt < 2; mt++)
#pragma unroll
        for (int nt = 0; nt < 4; nt++) {
            d[mt][nt][0] = 0.f; d[mt][nt][1] = 0.f;
            d[mt][nt][2] = 0.f; d[mt][nt][3] = 0.f;
        }

#pragma unroll
    for (int kt = 0; kt < EK + AK; kt++) {
        uint32_t ah[2][4], al[2][4];
#pragma unroll
        for (int mt = 0; mt < 2; mt++) {
            if (kt < EK) {
                ldsm4(ah[mt], eHi + mt * 16 * SE + kt * 32);
                ldsm4(al[mt], eHi + mt * 16 * SE + kt * 32 + ELO_DELTA);
            } else {
                ldsm4(ah[mt], aHi + mt * 16 * SA + (kt - EK) * 32);
                ldsm4(al[mt], aHi + mt * 16 * SA + (kt - EK) * 32 + ALO_DELTA);
            }
        }
#pragma unroll
        for (int n2 = 0; n2 < 2; n2++) {
            const uint32_t bp = bHi0 + kt * 32 + n2 * (16 * SB);
            uint32_t bh[4], bl[4];
            ldsm4(bh, bp);
            ldsm4(bl, bp + BLO_DELTA);
#pragma unroll
            for (int mt = 0; mt < 2; mt++) {
                mma16816(d[mt][2 * n2],     ah[mt], bh);
                mma16816(d[mt][2 * n2],     ah[mt], bl);
                mma16816(d[mt][2 * n2],     al[mt], bh);
                mma16816(d[mt][2 * n2 + 1], ah[mt], bh + 2);
                mma16816(d[mt][2 * n2 + 1], ah[mt], bl + 2);
                mma16816(d[mt][2 * n2 + 1], al[mt], bh + 2);
            }
        }
    }

    // All reads of B/act/enc complete block-wide before epilogue stores.
    __syncthreads();
    if (nextL >= 0) copyB_async(sb, nextL);    // overlap copy with epilogue

    // ---- epilogue (rows 32wm+{0..31}; cols wg*32 .. wg*32+31) ----
    const bool relu  = flags & F_RELU;
    const bool store = flags & F_STORE;
    const float* wc1  = reinterpret_cast<const float*>(sm + WC1_OFF);
    const float* bcol = reinterpret_cast<const float*>(sm + BCOL_OFF);

#pragma unroll
    for (int mt = 0; mt < 2; mt++) {
        const int r0 = 32 * wm + 16 * mt + rh;   // and r0+8
        if ((flags & F_DENS) && wg == 0 && q == 0) {
            reinterpret_cast<float*>(sm + DENS_OFF)[r0]     = d[mt][0][0];
            reinterpret_cast<float*>(sm + DENS_OFF)[r0 + 8] = d[mt][0][2];
        }
        float b0 = 0.f, b1 = 0.f;
        float g00 = 0.f, g01 = 0.f, g02 = 0.f, g10 = 0.f, g11 = 0.f, g12 = 0.f;
#pragma unroll
        for (int nt = 0; nt < 4; nt++) {
            float f00 = d[mt][nt][0], f01 = d[mt][nt][1];
            float f10 = d[mt][nt][2], f11 = d[mt][nt][3];
            if (relu) {
                f00 = fmaxf(f00, 0.f); f01 = fmaxf(f01, 0.f);
                f10 = fmaxf(f10, 0.f); f11 = fmaxf(f11, 0.f);
            }
            const int c = wg * 32 + nt * 8 + 2 * q;
            if (flags & F_BLEND) {
                b0 = fmaf(f00, bcol[c], fmaf(f01, bcol[c + 1], b0));
                b1 = fmaf(f10, bcol[c], fmaf(f11, bcol[c + 1], b1));
            }
            if (flags & F_RGB) {
                g00 = fmaf(f00, wc1[c * 3 + 0], fmaf(f01, wc1[(c + 1) * 3 + 0], g00));
                g01 = fmaf(f00, wc1[c * 3 + 1], fmaf(f01, wc1[(c + 1) * 3 + 1], g01));
                g02 = fmaf(f00, wc1[c * 3 + 2], fmaf(f01, wc1[(c + 1) * 3 + 2], g02));
                g10 = fmaf(f10, wc1[c * 3 + 0], fmaf(f11, wc1[(c + 1) * 3 + 0], g10));
                g11 = fmaf(f10, wc1[c * 3 + 1], fmaf(f11, wc1[(c + 1) * 3 + 1], g11));
                g12 = fmaf(f10, wc1[c * 3 + 2], fmaf(f11, wc1[(c + 1) * 3 + 2], g12));
            }
            if (store) {
                uint32_t lp0, hp0 = packSplitHi(f00, f01, lp0);
                uint32_t lp1, hp1 = packSplitHi(f10, f11, lp1);
                char* p = sm + AHI_OFF + (uint32_t)r0 * SA + wg * 64 + nt * 16 + q * 4;
                *reinterpret_cast<uint32_t*>(p)                      = hp0;
                *reinterpret_cast<uint32_t*>(p + 8 * SA)             = hp1;
                *reinterpret_cast<uint32_t*>(p + ALO_DELTA)          = lp0;
                *reinterpret_cast<uint32_t*>(p + ALO_DELTA + 8 * SA) = lp1;
            }
        }
        if (flags & F_BLEND) {
            b0 += __shfl_xor_sync(0xffffffffu, b0, 1);
            b0 += __shfl_xor_sync(0xffffffffu, b0, 2);
            b1 += __shfl_xor_sync(0xffffffffu, b1, 1);
            b1 += __shfl_xor_sync(0xffffffffu, b1, 2);
            if (q == 0) {
                reinterpret_cast<float*>(sm + PB_OFF)[wg * 128 + r0]     = b0;
                reinterpret_cast<float*>(sm + PB_OFF)[wg * 128 + r0 + 8] = b1;
            }
        }
        if (flags & F_RGB) {
            g00 += __shfl_xor_sync(0xffffffffu, g00, 1); g00 += __shfl_xor_sync(0xffffffffu, g00, 2);
            g01 += __shfl_xor_sync(0xffffffffu, g01, 1); g01 += __shfl_xor_sync(0xffffffffu, g01, 2);
            g02 += __shfl_xor_sync(0xffffffffu, g02, 1); g02 += __shfl_xor_sync(0xffffffffu, g02, 2);
            g10 += __shfl_xor_sync(0xffffffffu, g10, 1); g10 += __shfl_xor_sync(0xffffffffu, g10, 2);
            g11 += __shfl_xor_sync(0xffffffffu, g11, 1); g11 += __shfl_xor_sync(0xffffffffu, g11, 2);
            g12 += __shfl_xor_sync(0xffffffffu, g12, 1); g12 += __shfl_xor_sync(0xffffffffu, g12, 2);
            if (q == 0) {
                float* pr = reinterpret_cast<float*>(sm + PR_OFF) + (wg * 128) * 3;
                pr[r0 * 3 + 0] = g00; pr[r0 * 3 + 1] = g01; pr[r0 * 3 + 2] = g02;
                pr[(r0 + 8) * 3 + 0] = g10; pr[(r0 + 8) * 3 + 1] = g11; pr[(r0 + 8) * 3 + 2] = g12;
            }
        }
    }
}

__global__ void __launch_bounds__(BLOCK, 1)
nerf_mma_kernel(const float* __restrict__ x, const float* __restrict__ Wd2_3,
                const float* __restrict__ Wc_1, float* __restrict__ out, int N) {
    extern __shared__ char sm[];
    const uint32_t sb = smem_u32(sm);
    const int t = threadIdx.x;
    const int i0 = blockIdx.x * PTS;

    copyB_async(sb, 0);

    for (int idx = t; idx < 384; idx += BLOCK)
        reinterpret_cast<float*>(sm + WC1_OFF)[idx] = Wc_1[idx];
    if (t < 128) reinterpret_cast<float*>(sm + BCOL_OFF)[t] = Wd2_3[t * 129];

    float vx = 0.f, vy = 0.f, vz = 0.f;
    if (t < PTS) {
        int i = i0 + t;
        float p0 = 0.f, p1 = 0.f, p2 = 0.f;
        if (i < N) {
            const float* xp = x + 6 * i;
            p0 = xp[0]; p1 = xp[1]; p2 = xp[2];
            vx = xp[3]; vy = xp[4]; vz = xp[5];
        }
#pragma unroll
        for (int dd = 0; dd < 3; dd++) {
            float base = (dd == 0) ? p0 : ((dd == 1) ? p1 : p2);
#pragma unroll
            for (int f = 0; f < 10; f++) {
                float s, c;
                sincosf(base * (CUDART_PI_F * (float)(1 << f)), &s, &c);
                encStore(sm, t, dd * 20 + 2 * f, s, c);
            }
        }
        encStore(sm, t, 60, 0.f, 0.f);
        encStore(sm, t, 62, 0.f, 0.f);
    }

    CP_WAIT0(); __syncthreads();
    layerT<4, 0, 144>(sm, sb, F_RELU | F_STORE, 1);              // L1

    CP_WAIT0(); __syncthreads();
    layerT<0, 8, 272>(sm, sb, F_RELU | F_STORE, 2);              // L2

    CP_WAIT0(); __syncthreads();
    layerT<0, 8, 272>(sm, sb, F_STORE, 3);                       // L3 (linear)

    CP_WAIT0(); __syncthreads();
    layerT<4, 8, 400>(sm, sb, F_RELU | F_STORE, 4);              // L4

    // enc_pos reads finished inside layerT(L4)'s barrier -> write view enc now
    if (t < PTS) {
#pragma unroll
        for (int dd = 0; dd < 3; dd++) {
            float base = (dd == 0) ? vx : ((dd == 1) ? vy : vz);
#pragma unroll
            for (int f = 0; f < 4; f++) {
                float s, c;
                sincosf(base * (CUDART_PI_F * (float)(1 << f)), &s, &c);
                encStore(sm, t, dd * 8 + 2 * f, s, c);
            }
        }
        encStore(sm, t, 24, 0.f, 0.f);
        encStore(sm, t, 26, 0.f, 0.f);
        encStore(sm, t, 28, 0.f, 0.f);
        encStore(sm, t, 30, 0.f, 0.f);
    }

    CP_WAIT0(); __syncthreads();
    layerT<0, 8, 272>(sm, sb, F_RELU | F_STORE, 5);              // L5

    CP_WAIT0(); __syncthreads();
    layerT<0, 8, 272>(sm, sb, F_RELU | F_STORE | F_BLEND, 6);    // L6

    CP_WAIT0(); __syncthreads();
    layerT<0, 8, 272>(sm, sb, F_STORE | F_DENS, 7);              // L7 (linear)

    CP_WAIT0(); __syncthreads();
    layerT<2, 8, 336>(sm, sb, F_RELU | F_RGB, -1);               // L8

    __syncthreads();
    if (t < PTS) {
        int i = i0 + t;
        if (i < N) {
            const float* pr = reinterpret_cast<const float*>(sm + PR_OFF);
            const float* pb = reinterpret_cast<const float*>(sm + PB_OFF);
            float braw = pb[t] + pb[128 + t] + pb[256 + t] + pb[384 + t];
            float r0 = 0.f, r1 = 0.f, r2 = 0.f;
#pragma unroll
            for (int g = 0; g < 4; g++) {
                r0 += pr[(g * 128 + t) * 3 + 0];
                r1 += pr[(g * 128 + t) * 3 + 1];
                r2 += pr[(g * 128 + t) * 3 + 2];
            }
            float* o = out + 5 * i;
            o[0] = r0;
            o[1] = r1;
            o[2] = r2;
            o[3] = reinterpret_cast<const float*>(sm + DENS_OFF)[t];
            o[4] = 1.f / (1.f + expf(-braw));
        }
    }
}

extern "C" void kernel_launch(void* const* d_in, const int* in_sizes, int n_in,
                              void* d_out, int out_size) {
    const float* x     = (const float*)d_in[0];
    const float* Wd1_0 = (const float*)d_in[1];
    const float* Wd1_1 = (const float*)d_in[2];
    const float* Wd1_2 = (const float*)d_in[3];
    const float* Wd2_0 = (const float*)d_in[4];
    const float* Wd2_1 = (const float*)d_in[5];
    const float* Wd2_2 = (const float*)d_in[6];
    const float* Wd2_3 = (const float*)d_in[7];
    const float* Wc_0  = (const float*)d_in[8];
    const float* Wc_1  = (const float*)d_in[9];
    float* out = (float*)d_out;

    int N = in_sizes[0] / 6;
    if (N <= 0) return;

    prepass_kernel<<<(143360 + 255) / 256, 256>>>(Wd1_0, Wd1_1, Wd1_2, Wd2_0,
                                                  Wd2_1, Wd2_2, Wd2_3, Wc_0);

    cudaFuncSetAttribute(nerf_mma_kernel,
                         cudaFuncAttributeMaxDynamicSharedMemorySize, SMEM_BYTES);
    int grid = (N + PTS - 1) / PTS;
    nerf_mma_kernel<<<grid, BLOCK, SMEM_BYTES>>>(x, Wd2_3, Wc_1, out, N);
}

// round 11
// speedup vs baseline: 4.9337x; 1.2575x over previous
#include <cuda_runtime.h>
#include <cuda_fp16.h>
#include <math_constants.h>
#include <cstdint>

#define BLOCK 512
#define PTS   128

// ---- smem byte offsets ----
#define AHI_OFF   0         // act hi  [128][136] fp16 (stride 272B) = 34816
#define ALO_OFF   34816     // act lo
#define EHI_OFF   69632     // enc hi  [128][72] fp16 (stride 144B) = 18432
#define ELO_OFF   88064     // enc lo
#define B0_OFF    106496    // weight buffer 0 (single fp16 plane, max 200*128*2=51200)
#define B1_OFF    157696    // weight buffer 1
#define WC1_OFF   208896    // Wc_1 fp32 [128][3]
#define BCOL_OFF  210432    // Wd2_3 col0 fp32 [128]
#define DENS_OFF  210944    // density fp32 [128]
#define PB_OFF    211456    // blend partials fp32 [4][128]
#define PR_OFF    213504    // rgb partials fp32 [4][128][3]
#define SMEM_BYTES 219648

#define SA 272
#define SE 144
#define ALO_DELTA 34816
#define ELO_DELTA 18432

// epilogue flag bits
#define F_RELU  1
#define F_STORE 2
#define F_DENS  4
#define F_BLEND 8
#define F_RGB   16

// ---- pre-converted weights: Bt[j][k] row-major, padded, single fp16 plane ----
__device__ __half g_w[143360];

__constant__ int c_loff[9] = {0, 9216, 26624, 44032, 69632, 87040, 104448, 121856, 143360};
__constant__ int c_kpad[8] = {72, 136, 136, 200, 136, 136, 136, 168};
__constant__ int c_n16[8]  = {1152, 2176, 2176, 3200, 2176, 2176, 2176, 2688};

__global__ void prepass_kernel(const float* __restrict__ Wd1_0, const float* __restrict__ Wd1_1,
                               const float* __restrict__ Wd1_2, const float* __restrict__ Wd2_0,
                               const float* __restrict__ Wd2_1, const float* __restrict__ Wd2_2,
                               const float* __restrict__ Wd2_3, const float* __restrict__ Wc_0) {
    int e = blockIdx.x * blockDim.x + threadIdx.x;
    if (e >= 143360) return;
    int l = 0;
    while (e >= c_loff[l + 1]) l++;
    int r = e - c_loff[l];
    int kp = c_kpad[l];
    int j = r / kp;
    int k = r % kp;
    float v = 0.f;
    switch (l) {
        case 0: if (k < 60) v = Wd1_0[k * 128 + j]; break;
        case 1: if (k < 128) v = Wd1_1[k * 128 + j]; break;
        case 2: if (k < 128) v = Wd1_2[k * 128 + j]; break;
        case 3: if (k < 60) v = Wd2_0[k * 128 + j];
                else if (k >= 64 && k < 192) v = Wd2_0[(k - 4) * 128 + j];
                break;
        case 4: if (k < 128) v = Wd2_1[k * 128 + j]; break;
        case 5: if (k < 128) v = Wd2_2[k * 128 + j]; break;
        case 6: if (k < 128) v = Wd2_3[k * 129 + (j + 1)]; break;  // rotated
        case 7: if (k < 24) v = Wc_0[k * 128 + j];
                else if (k >= 32 && k < 160) v = Wc_0[(k - 8) * 128 + j];
                break;
    }
    g_w[e] = __float2half_rn(v);
}

// ---- helpers ----
__device__ __forceinline__ void mma16816(float* d, const uint32_t* a, const uint32_t* b) {
    asm volatile(
        "mma.sync.aligned.m16n8k16.row.col.f32.f16.f16.f32 "
        "{%0,%1,%2,%3}, {%4,%5,%6,%7}, {%8,%9}, {%0,%1,%2,%3};"
        : "+f"(d[0]), "+f"(d[1]), "+f"(d[2]), "+f"(d[3])
        : "r"(a[0]), "r"(a[1]), "r"(a[2]), "r"(a[3]), "r"(b[0]), "r"(b[1]));
}

__device__ __forceinline__ void ldsm4(uint32_t* r, uint32_t addr) {
    asm volatile("ldmatrix.sync.aligned.m8n8.x4.shared.b16 {%0,%1,%2,%3}, [%4];"
                 : "=r"(r[0]), "=r"(r[1]), "=r"(r[2]), "=r"(r[3]) : "r"(addr));
}

__device__ __forceinline__ void cpasync16(uint32_t dst, const void* src) {
    asm volatile("cp.async.cg.shared.global [%0], [%1], 16;" :: "r"(dst), "l"(src));
}
#define CP_COMMIT() asm volatile("cp.async.commit_group;")
#define CP_WAIT0()  asm volatile("cp.async.wait_group 0;" ::: "memory")

__device__ __forceinline__ uint32_t smem_u32(const void* p) {
    uint32_t a;
    asm("{ .reg .u64 t; cvta.to.shared.u64 t, %1; cvt.u32.u64 %0, t; }" : "=r"(a) : "l"(p));
    return a;
}

__device__ __forceinline__ uint32_t packSplitHi(float f0, float f1, uint32_t& lp) {
    __half h0 = __float2half_rn(f0), h1 = __float2half_rn(f1);
    __half l0 = __float2half_rn(f0 - __half2float(h0));
    __half l1 = __float2half_rn(f1 - __half2float(h1));
    lp = ((uint32_t)__half_as_ushort(l1) << 16) | __half_as_ushort(l0);
    return ((uint32_t)__half_as_ushort(h1) << 16) | __half_as_ushort(h0);
}

__device__ __forceinline__ void encStore(char* sm, int row, int col, float f0, float f1) {
    uint32_t lp, hp = packSplitHi(f0, f1, lp);
    *reinterpret_cast<uint32_t*>(sm + EHI_OFF + row * SE + col * 2) = hp;
    *reinterpret_cast<uint32_t*>(sm + ELO_OFF + row * SE + col * 2) = lp;
}

__device__ __forceinline__ void copyB_async(uint32_t sb, int l, uint32_t bufOff) {
    const int n16 = c_n16[l];
    const char* src = reinterpret_cast<const char*>(g_w + c_loff[l]);
    const uint32_t dst = sb + bufOff;
    for (int i = threadIdx.x; i < n16; i += BLOCK)
        cpasync16(dst + i * 16, src + i * 16);
    CP_COMMIT();
}

// One layer: EK enc k-tiles + AK act k-tiles, weight row stride SB bytes.
// 16 warps, warp tile 32 rows x 32 cols. 2-pass fp16: D = Ahi*B + Alo*B.
// Mid-barrier separates all act/enc/B reads from act stores; relu/aux/hi-pack
// done pre-barrier, lo-pack recycled into accumulator registers.
template<int EK, int AK, int SB>
__device__ __noinline__ void layerT(char* sm, uint32_t sb, uint32_t bufOff, int flags) {
    const int t = threadIdx.x;
    const int w = t >> 5, lane = t & 31;
    const int wm = w & 3, wg = w >> 2;
    const int q = lane & 3, rh = lane >> 2;
    const int arow = lane & 15, asel = lane >> 4;
    const int brow = (lane & 7) + ((lane >> 4) << 3);
    const int bsel = (lane >> 3) & 1;

    const uint32_t aHi = sb + AHI_OFF + (uint32_t)(32 * wm + arow) * SA + asel * 16;
    const uint32_t eHi = sb + EHI_OFF + (uint32_t)(32 * wm + arow) * SE + asel * 16;
    const uint32_t bB0 = sb + bufOff + (uint32_t)(brow + wg * 32) * SB + bsel * 16;

    float d[2][4][4];
#pragma unroll
    for (int mt = 0; mt < 2; mt++)
#pragma unroll
        for (int nt = 0; nt < 4; nt++) {
            d[mt][nt][0] = 0.f; d[mt][nt][1] = 0.f;
            d[mt][nt][2] = 0.f; d[mt][nt][3] = 0.f;
        }

#pragma unroll
    for (int kt = 0; kt < EK + AK; kt++) {
        uint32_t ah[2][4], al[2][4];
#pragma unroll
        for (int mt = 0; mt < 2; mt++) {
            if (kt < EK) {
                ldsm4(ah[mt], eHi + mt * 16 * SE + kt * 32);
                ldsm4(al[mt], eHi + mt * 16 * SE + kt * 32 + ELO_DELTA);
            } else {
                ldsm4(ah[mt], aHi + mt * 16 * SA + (kt - EK) * 32);
                ldsm4(al[mt], aHi + mt * 16 * SA + (kt - EK) * 32 + ALO_DELTA);
            }
        }
#pragma unroll
        for (int n2 = 0; n2 < 2; n2++) {
            const uint32_t bp = bB0 + kt * 32 + n2 * (16 * SB);
            uint32_t bh[4];
            ldsm4(bh, bp);
#pragma unroll
            for (int mt = 0; mt < 2; mt++) {
                mma16816(d[mt][2 * n2],     ah[mt], bh);
                mma16816(d[mt][2 * n2],     al[mt], bh);
                mma16816(d[mt][2 * n2 + 1], ah[mt], bh + 2);
                mma16816(d[mt][2 * n2 + 1], al[mt], bh + 2);
            }
        }
    }

    // ---- pre-barrier epilogue: relu (in place), aux partials, hi-pack ----
    const bool relu  = flags & F_RELU;
    const bool store = flags & F_STORE;
    const float* wc1  = reinterpret_cast<const float*>(sm + WC1_OFF);
    const float* bcol = reinterpret_cast<const float*>(sm + BCOL_OFF);
    uint32_t hpack[2][4][2];

#pragma unroll
    for (int mt = 0; mt < 2; mt++) {
        const int r0 = 32 * wm + 16 * mt + rh;
        if ((flags & F_DENS) && wg == 0 && q == 0) {
            reinterpret_cast<float*>(sm + DENS_OFF)[r0]     = d[mt][0][0];
            reinterpret_cast<float*>(sm + DENS_OFF)[r0 + 8] = d[mt][0][2];
        }
        float b0 = 0.f, b1 = 0.f;
        float g00 = 0.f, g01 = 0.f, g02 = 0.f, g10 = 0.f, g11 = 0.f, g12 = 0.f;
#pragma unroll
        for (int nt = 0; nt < 4; nt++) {
            float f00 = d[mt][nt][0], f01 = d[mt][nt][1];
            float f10 = d[mt][nt][2], f11 = d[mt][nt][3];
            if (relu) {
                f00 = fmaxf(f00, 0.f); f01 = fmaxf(f01, 0.f);
                f10 = fmaxf(f10, 0.f); f11 = fmaxf(f11, 0.f);
            }
            const int c = wg * 32 + nt * 8 + 2 * q;
            if (flags & F_BLEND) {
                b0 = fmaf(f00, bcol[c], fmaf(f01, bcol[c + 1], b0));
                b1 = fmaf(f10, bcol[c], fmaf(f11, bcol[c + 1], b1));
            }
            if (flags & F_RGB) {
                g00 = fmaf(f00, wc1[c * 3 + 0], fmaf(f01, wc1[(c + 1) * 3 + 0], g00));
                g01 = fmaf(f00, wc1[c * 3 + 1], fmaf(f01, wc1[(c + 1) * 3 + 1], g01));
                g02 = fmaf(f00, wc1[c * 3 + 2], fmaf(f01, wc1[(c + 1) * 3 + 2], g02));
                g10 = fmaf(f10, wc1[c * 3 + 0], fmaf(f11, wc1[(c + 1) * 3 + 0], g10));
                g11 = fmaf(f10, wc1[c * 3 + 1], fmaf(f11, wc1[(c + 1) * 3 + 1], g11));
                g12 = fmaf(f10, wc1[c * 3 + 2], fmaf(f11, wc1[(c + 1) * 3 + 2], g12));
            }
            if (store) {
                uint32_t lp0, lp1;
                hpack[mt][nt][0] = packSplitHi(f00, f01, lp0);
                hpack[mt][nt][1] = packSplitHi(f10, f11, lp1);
                d[mt][nt][0] = __uint_as_float(lp0);   // recycle dead accum regs
                d[mt][nt][1] = __uint_as_float(lp1);
            }
        }
        if (flags & F_BLEND) {
            b0 += __shfl_xor_sync(0xffffffffu, b0, 1);
            b0 += __shfl_xor_sync(0xffffffffu, b0, 2);
            b1 += __shfl_xor_sync(0xffffffffu, b1, 1);
            b1 += __shfl_xor_sync(0xffffffffu, b1, 2);
            if (q == 0) {
                reinterpret_cast<float*>(sm + PB_OFF)[wg * 128 + r0]     = b0;
                reinterpret_cast<float*>(sm + PB_OFF)[wg * 128 + r0 + 8] = b1;
            }
        }
        if (flags & F_RGB) {
            g00 += __shfl_xor_sync(0xffffffffu, g00, 1); g00 += __shfl_xor_sync(0xffffffffu, g00, 2);
            g01 += __shfl_xor_sync(0xffffffffu, g01, 1); g01 += __shfl_xor_sync(0xffffffffu, g01, 2);
            g02 += __shfl_xor_sync(0xffffffffu, g02, 1); g02 += __shfl_xor_sync(0xffffffffu, g02, 2);
            g10 += __shfl_xor_sync(0xffffffffu, g10, 1); g10 += __shfl_xor_sync(0xffffffffu, g10, 2);
            g11 += __shfl_xor_sync(0xffffffffu, g11, 1); g11 += __shfl_xor_sync(0xffffffffu, g11, 2);
            g12 += __shfl_xor_sync(0xffffffffu, g12, 1); g12 += __shfl_xor_sync(0xffffffffu, g12, 2);
            if (q == 0) {
                float* pr = reinterpret_cast<float*>(sm + PR_OFF) + (wg * 128) * 3;
                pr[r0 * 3 + 0] = g00; pr[r0 * 3 + 1] = g01; pr[r0 * 3 + 2] = g02;
                pr[(r0 + 8) * 3 + 0] = g10; pr[(r0 + 8) * 3 + 1] = g11; pr[(r0 + 8) * 3 + 2] = g12;
            }
        }
    }

    // All mainloop reads complete block-wide before act stores.
    __syncthreads();

    if (store) {
#pragma unroll
        for (int mt = 0; mt < 2; mt++) {
            const int r0 = 32 * wm + 16 * mt + rh;
#pragma unroll
            for (int nt = 0; nt < 4; nt++) {
                char* p = sm + AHI_OFF + (uint32_t)r0 * SA + wg * 64 + nt * 16 + q * 4;
                *reinterpret_cast<uint32_t*>(p)                      = hpack[mt][nt][0];
                *reinterpret_cast<uint32_t*>(p + 8 * SA)             = hpack[mt][nt][1];
                *reinterpret_cast<uint32_t*>(p + ALO_DELTA)          = __float_as_uint(d[mt][nt][0]);
                *reinterpret_cast<uint32_t*>(p + ALO_DELTA + 8 * SA) = __float_as_uint(d[mt][nt][1]);
            }
        }
    }
}

__global__ void __launch_bounds__(BLOCK, 1)
nerf_mma_kernel(const float* __restrict__ x, const float* __restrict__ Wd2_3,
                const float* __restrict__ Wc_1, float* __restrict__ out, int N) {
    extern __shared__ char sm[];
    const uint32_t sb = smem_u32(sm);
    const int t = threadIdx.x;
    const int i0 = blockIdx.x * PTS;

    copyB_async(sb, 0, B0_OFF);

    for (int idx = t; idx < 384; idx += BLOCK)
        reinterpret_cast<float*>(sm + WC1_OFF)[idx] = Wc_1[idx];
    if (t < 128) reinterpret_cast<float*>(sm + BCOL_OFF)[t] = Wd2_3[t * 129];

    float vx = 0.f, vy = 0.f, vz = 0.f;
    if (t < PTS) {
        int i = i0 + t;
        float p0 = 0.f, p1 = 0.f, p2 = 0.f;
        if (i < N) {
            const float* xp = x + 6 * i;
            p0 = xp[0]; p1 = xp[1]; p2 = xp[2];
            vx = xp[3]; vy = xp[4]; vz = xp[5];
        }
#pragma unroll
        for (int dd = 0; dd < 3; dd++) {
            float base = (dd == 0) ? p0 : ((dd == 1) ? p1 : p2);
#pragma unroll
            for (int f = 0; f < 10; f++) {
                float s, c;
                sincosf(base * (CUDART_PI_F * (float)(1 << f)), &s, &c);
                encStore(sm, t, dd * 20 + 2 * f, s, c);
            }
        }
        encStore(sm, t, 60, 0.f, 0.f);
        encStore(sm, t, 62, 0.f, 0.f);
    }

    CP_WAIT0(); __syncthreads();
    copyB_async(sb, 1, B1_OFF);
    layerT<4, 0, 144>(sm, sb, B0_OFF, F_RELU | F_STORE);             // L1

    CP_WAIT0(); __syncthreads();
    copyB_async(sb, 2, B0_OFF);
    layerT<0, 8, 272>(sm, sb, B1_OFF, F_RELU | F_STORE);             // L2

    CP_WAIT0(); __syncthreads();
    copyB_async(sb, 3, B1_OFF);
    layerT<0, 8, 272>(sm, sb, B0_OFF, F_STORE);                      // L3 (linear)

    CP_WAIT0(); __syncthreads();
    copyB_async(sb, 4, B0_OFF);
    layerT<4, 8, 400>(sm, sb, B1_OFF, F_RELU | F_STORE);             // L4

    // enc_pos reads finished at L4's mid-barrier -> write view enc now
    if (t < PTS) {
#pragma unroll
        for (int dd = 0; dd < 3; dd++) {
            float base = (dd == 0) ? vx : ((dd == 1) ? vy : vz);
#pragma unroll
            for (int f = 0; f < 4; f++) {
                float s, c;
                sincosf(base * (CUDART_PI_F * (float)(1 << f)), &s, &c);
                encStore(sm, t, dd * 8 + 2 * f, s, c);
            }
        }
        encStore(sm, t, 24, 0.f, 0.f);
        encStore(sm, t, 26, 0.f, 0.f);
        encStore(sm, t, 28, 0.f, 0.f);
        encStore(sm, t, 30, 0.f, 0.f);
    }

    CP_WAIT0(); __syncthreads();
    copyB_async(sb, 5, B1_OFF);
    layerT<0, 8, 272>(sm, sb, B0_OFF, F_RELU | F_STORE);             // L5

    CP_WAIT0(); __syncthreads();
    copyB_async(sb, 6, B0_OFF);
    layerT<0, 8, 272>(sm, sb, B1_OFF, F_RELU | F_STORE | F_BLEND);   // L6

    CP_WAIT0(); __syncthreads();
    copyB_async(sb, 7, B1_OFF);
    layerT<0, 8, 272>(sm, sb, B0_OFF, F_STORE | F_DENS);             // L7 (linear)

    CP_WAIT0(); __syncthreads();
    layerT<2, 8, 336>(sm, sb, B1_OFF, F_RELU | F_RGB);               // L8

    __syncthreads();
    if (t < PTS) {
        int i = i0 + t;
        if (i < N) {
            const float* pr = reinterpret_cast<const float*>(sm + PR_OFF);
            const float* pb = reinterpret_cast<const float*>(sm + PB_OFF);
            float braw = pb[t] + pb[128 + t] + pb[256 + t] + pb[384 + t];
            float r0 = 0.f, r1 = 0.f, r2 = 0.f;
#pragma unroll
            for (int g = 0; g < 4; g++) {
                r0 += pr[(g * 128 + t) * 3 + 0];
                r1 += pr[(g * 128 + t) * 3 + 1];
                r2 += pr[(g * 128 + t) * 3 + 2];
            }
            float* o = out + 5 * i;
            o[0] = r0;
            o[1] = r1;
            o[2] = r2;
            o[3] = reinterpret_cast<const float*>(sm + DENS_OFF)[t];
            o[4] = 1.f / (1.f + expf(-braw));
        }
    }
}

extern "C" void kernel_launch(void* const* d_in, const int* in_sizes, int n_in,
                              void* d_out, int out_size) {
    const float* x     = (const float*)d_in[0];
    const float* Wd1_0 = (const float*)d_in[1];
    const float* Wd1_1 = (const float*)d_in[2];
    const float* Wd1_2 = (const float*)d_in[3];
    const float* Wd2_0 = (const float*)d_in[4];
    const float* Wd2_1 = (const float*)d_in[5];
    const float* Wd2_2 = (const float*)d_in[6];
    const float* Wd2_3 = (const float*)d_in[7];
    const float* Wc_0  = (const float*)d_in[8];
    const float* Wc_1  = (const float*)d_in[9];
    float* out = (float*)d_out;

    int N = in_sizes[0] / 6;
    if (N <= 0) return;

    prepass_kernel<<<(143360 + 255) / 256, 256>>>(Wd1_0, Wd1_1, Wd1_2, Wd2_0,
                                                  Wd2_1, Wd2_2, Wd2_3, Wc_0);

    cudaFuncSetAttribute(nerf_mma_kernel,
                         cudaFuncAttributeMaxDynamicSharedMemorySize, SMEM_BYTES);
    int grid = (N + PTS - 1) / PTS;
    nerf_mma_kernel<<<grid, BLOCK, SMEM_BYTES>>>(x, Wd2_3, Wc_1, out, N);
}

// round 12
// speedup vs baseline: 4.9631x; 1.0060x over previous
#include <cuda_runtime.h>
#include <cuda_fp16.h>
#include <math_constants.h>
#include <cstdint>

#define BLOCK 512
#define PTS   128

// ---- smem byte offsets ----
#define AHI_OFF   0         // act hi  [128][136] fp16 (stride 272B) = 34816
#define ALO_OFF   34816     // act lo
#define EHI_OFF   69632     // enc hi  [128][72] fp16 (stride 144B) = 18432
#define ELO_OFF   88064     // enc lo
#define B0_OFF    106496    // weight buffer 0 (single fp16 plane, max 200*128*2=51200)
#define B1_OFF    157696    // weight buffer 1
#define WC1_OFF   208896    // Wc_1 fp32 [128][3]
#define BCOL_OFF  210432    // Wd2_3 col0 fp32 [128]
#define DENS_OFF  210944    // density fp32 [128]
#define PB_OFF    211456    // blend partials fp32 [4][128]
#define PR_OFF    213504    // rgb partials fp32 [4][128][3]
#define SMEM_BYTES 219648

#define SA 272
#define SE 144
#define ALO_DELTA 34816
#define ELO_DELTA 18432

// epilogue flag bits
#define F_RELU  1
#define F_STORE 2
#define F_DENS  4
#define F_BLEND 8
#define F_RGB   16

// ---- pre-converted weights: Bt[j][k] row-major, padded, single fp16 plane ----
__device__ __half g_w[143360];

__constant__ int c_loff[9] = {0, 9216, 26624, 44032, 69632, 87040, 104448, 121856, 143360};
__constant__ int c_kpad[8] = {72, 136, 136, 200, 136, 136, 136, 168};
__constant__ int c_n16[8]  = {1152, 2176, 2176, 3200, 2176, 2176, 2176, 2688};

__global__ void prepass_kernel(const float* __restrict__ Wd1_0, const float* __restrict__ Wd1_1,
                               const float* __restrict__ Wd1_2, const float* __restrict__ Wd2_0,
                               const float* __restrict__ Wd2_1, const float* __restrict__ Wd2_2,
                               const float* __restrict__ Wd2_3, const float* __restrict__ Wc_0) {
    int e = blockIdx.x * blockDim.x + threadIdx.x;
    if (e >= 143360) return;
    int l = 0;
    while (e >= c_loff[l + 1]) l++;
    int r = e - c_loff[l];
    int kp = c_kpad[l];
    int j = r / kp;
    int k = r % kp;
    float v = 0.f;
    switch (l) {
        case 0: if (k < 60) v = Wd1_0[k * 128 + j]; break;
        case 1: if (k < 128) v = Wd1_1[k * 128 + j]; break;
        case 2: if (k < 128) v = Wd1_2[k * 128 + j]; break;
        case 3: if (k < 60) v = Wd2_0[k * 128 + j];
                else if (k >= 64 && k < 192) v = Wd2_0[(k - 4) * 128 + j];
                break;
        case 4: if (k < 128) v = Wd2_1[k * 128 + j]; break;
        case 5: if (k < 128) v = Wd2_2[k * 128 + j]; break;
        case 6: if (k < 128) v = Wd2_3[k * 129 + (j + 1)]; break;  // rotated
        case 7: if (k < 24) v = Wc_0[k * 128 + j];
                else if (k >= 32 && k < 160) v = Wc_0[(k - 8) * 128 + j];
                break;
    }
    g_w[e] = __float2half_rn(v);
}

// ---- helpers ----
__device__ __forceinline__ void mma16816(float* d, const uint32_t* a, const uint32_t* b) {
    asm volatile(
        "mma.sync.aligned.m16n8k16.row.col.f32.f16.f16.f32 "
        "{%0,%1,%2,%3}, {%4,%5,%6,%7}, {%8,%9}, {%0,%1,%2,%3};"
        : "+f"(d[0]), "+f"(d[1]), "+f"(d[2]), "+f"(d[3])
        : "r"(a[0]), "r"(a[1]), "r"(a[2]), "r"(a[3]), "r"(b[0]), "r"(b[1]));
}

__device__ __forceinline__ void ldsm4(uint32_t* r, uint32_t addr) {
    asm volatile("ldmatrix.sync.aligned.m8n8.x4.shared.b16 {%0,%1,%2,%3}, [%4];"
                 : "=r"(r[0]), "=r"(r[1]), "=r"(r[2]), "=r"(r[3]) : "r"(addr));
}

__device__ __forceinline__ void cpasync16(uint32_t dst, const void* src) {
    asm volatile("cp.async.cg.shared.global [%0], [%1], 16;" :: "r"(dst), "l"(src));
}
#define CP_COMMIT() asm volatile("cp.async.commit_group;")
#define CP_WAIT0()  asm volatile("cp.async.wait_group 0;" ::: "memory")

__device__ __forceinline__ uint32_t smem_u32(const void* p) {
    uint32_t a;
    asm("{ .reg .u64 t; cvta.to.shared.u64 t, %1; cvt.u32.u64 %0, t; }" : "=r"(a) : "l"(p));
    return a;
}

__device__ __forceinline__ uint32_t packSplitHi(float f0, float f1, uint32_t& lp) {
    __half h0 = __float2half_rn(f0), h1 = __float2half_rn(f1);
    __half l0 = __float2half_rn(f0 - __half2float(h0));
    __half l1 = __float2half_rn(f1 - __half2float(h1));
    lp = ((uint32_t)__half_as_ushort(l1) << 16) | __half_as_ushort(l0);
    return ((uint32_t)__half_as_ushort(h1) << 16) | __half_as_ushort(h0);
}

__device__ __forceinline__ void encStore(char* sm, int row, int col, float f0, float f1) {
    uint32_t lp, hp = packSplitHi(f0, f1, lp);
    *reinterpret_cast<uint32_t*>(sm + EHI_OFF + row * SE + col * 2) = hp;
    *reinterpret_cast<uint32_t*>(sm + ELO_OFF + row * SE + col * 2) = lp;
}

__device__ __forceinline__ void copyB_async(uint32_t sb, int l, uint32_t bufOff) {
    const int n16 = c_n16[l];
    const char* src = reinterpret_cast<const char*>(g_w + c_loff[l]);
    const uint32_t dst = sb + bufOff;
    for (int i = threadIdx.x; i < n16; i += BLOCK)
        cpasync16(dst + i * 16, src + i * 16);
    CP_COMMIT();
}

// One layer: EK enc k-tiles + AK act k-tiles, weight row stride SB bytes.
// 16 warps, warp tile 32 rows x 32 cols. 2-pass fp16: D = Ahi*B + Alo*B.
// R12: software-pipelined mainloop — A-hi and B fragments double-buffered
// (prefetch kt+1 before consuming kt), A-lo loaded at kt entry and consumed
// after the hi-MMAs. Mid-barrier separates reads from act stores.
template<int EK, int AK, int SB>
__device__ __noinline__ void layerT(char* sm, uint32_t sb, uint32_t bufOff, int flags) {
    const int t = threadIdx.x;
    const int w = t >> 5, lane = t & 31;
    const int wm = w & 3, wg = w >> 2;
    const int q = lane & 3, rh = lane >> 2;
    const int arow = lane & 15, asel = lane >> 4;
    const int brow = (lane & 7) + ((lane >> 4) << 3);
    const int bsel = (lane >> 3) & 1;
    constexpr int TOT = EK + AK;

    const uint32_t aHi = sb + AHI_OFF + (uint32_t)(32 * wm + arow) * SA + asel * 16;
    const uint32_t eHi = sb + EHI_OFF + (uint32_t)(32 * wm + arow) * SE + asel * 16;
    const uint32_t bB0 = sb + bufOff + (uint32_t)(brow + wg * 32) * SB + bsel * 16;

    auto loadAhi = [&](int kt, uint32_t dst[2][4]) {
        if (kt < EK) {
            ldsm4(dst[0], eHi + kt * 32);
            ldsm4(dst[1], eHi + 16 * SE + kt * 32);
        } else {
            ldsm4(dst[0], aHi + (kt - EK) * 32);
            ldsm4(dst[1], aHi + 16 * SA + (kt - EK) * 32);
        }
    };
    auto loadAlo = [&](int kt, uint32_t dst[2][4]) {
        if (kt < EK) {
            ldsm4(dst[0], eHi + kt * 32 + ELO_DELTA);
            ldsm4(dst[1], eHi + 16 * SE + kt * 32 + ELO_DELTA);
        } else {
            ldsm4(dst[0], aHi + (kt - EK) * 32 + ALO_DELTA);
            ldsm4(dst[1], aHi + 16 * SA + (kt - EK) * 32 + ALO_DELTA);
        }
    };
    auto loadB = [&](int kt, uint32_t dst[2][4]) {
        ldsm4(dst[0], bB0 + kt * 32);
        ldsm4(dst[1], bB0 + kt * 32 + 16 * SB);
    };

    float d[2][4][4];
#pragma unroll
    for (int mt = 0; mt < 2; mt++)
#pragma unroll
        for (int nt = 0; nt < 4; nt++) {
            d[mt][nt][0] = 0.f; d[mt][nt][1] = 0.f;
            d[mt][nt][2] = 0.f; d[mt][nt][3] = 0.f;
        }

    uint32_t ah[2][2][4], bhf[2][2][4], al[2][4];
    loadAhi(0, ah[0]);
    loadB(0, bhf[0]);

#pragma unroll
    for (int kt = 0; kt < TOT; kt++) {
        const int cur = kt & 1, nxt = cur ^ 1;
        loadAlo(kt, al);
        if (kt + 1 < TOT) {
            loadAhi(kt + 1, ah[nxt]);
            loadB(kt + 1, bhf[nxt]);
        }
#pragma unroll
        for (int n2 = 0; n2 < 2; n2++)
#pragma unroll
            for (int mt = 0; mt < 2; mt++) {
                mma16816(d[mt][2 * n2],     ah[cur][mt], bhf[cur][n2]);
                mma16816(d[mt][2 * n2 + 1], ah[cur][mt], bhf[cur][n2] + 2);
            }
#pragma unroll
        for (int n2 = 0; n2 < 2; n2++)
#pragma unroll
            for (int mt = 0; mt < 2; mt++) {
                mma16816(d[mt][2 * n2],     al[mt], bhf[cur][n2]);
                mma16816(d[mt][2 * n2 + 1], al[mt], bhf[cur][n2] + 2);
            }
    }

    // ---- pre-barrier epilogue: relu (in place), aux partials, hi-pack ----
    const bool relu  = flags & F_RELU;
    const bool store = flags & F_STORE;
    const float* wc1  = reinterpret_cast<const float*>(sm + WC1_OFF);
    const float* bcol = reinterpret_cast<const float*>(sm + BCOL_OFF);
    uint32_t hpack[2][4][2];

#pragma unroll
    for (int mt = 0; mt < 2; mt++) {
        const int r0 = 32 * wm + 16 * mt + rh;
        if ((flags & F_DENS) && wg == 0 && q == 0) {
            reinterpret_cast<float*>(sm + DENS_OFF)[r0]     = d[mt][0][0];
            reinterpret_cast<float*>(sm + DENS_OFF)[r0 + 8] = d[mt][0][2];
        }
        float b0 = 0.f, b1 = 0.f;
        float g00 = 0.f, g01 = 0.f, g02 = 0.f, g10 = 0.f, g11 = 0.f, g12 = 0.f;
#pragma unroll
        for (int nt = 0; nt < 4; nt++) {
            float f00 = d[mt][nt][0], f01 = d[mt][nt][1];
            float f10 = d[mt][nt][2], f11 = d[mt][nt][3];
            if (relu) {
                f00 = fmaxf(f00, 0.f); f01 = fmaxf(f01, 0.f);
                f10 = fmaxf(f10, 0.f); f11 = fmaxf(f11, 0.f);
            }
            const int c = wg * 32 + nt * 8 + 2 * q;
            if (flags & F_BLEND) {
                b0 = fmaf(f00, bcol[c], fmaf(f01, bcol[c + 1], b0));
                b1 = fmaf(f10, bcol[c], fmaf(f11, bcol[c + 1], b1));
            }
            if (flags & F_RGB) {
                g00 = fmaf(f00, wc1[c * 3 + 0], fmaf(f01, wc1[(c + 1) * 3 + 0], g00));
                g01 = fmaf(f00, wc1[c * 3 + 1], fmaf(f01, wc1[(c + 1) * 3 + 1], g01));
                g02 = fmaf(f00, wc1[c * 3 + 2], fmaf(f01, wc1[(c + 1) * 3 + 2], g02));
                g10 = fmaf(f10, wc1[c * 3 + 0], fmaf(f11, wc1[(c + 1) * 3 + 0], g10));
                g11 = fmaf(f10, wc1[c * 3 + 1], fmaf(f11, wc1[(c + 1) * 3 + 1], g11));
                g12 = fmaf(f10, wc1[c * 3 + 2], fmaf(f11, wc1[(c + 1) * 3 + 2], g12));
            }
            if (store) {
                uint32_t lp0, lp1;
                hpack[mt][nt][0] = packSplitHi(f00, f01, lp0);
                hpack[mt][nt][1] = packSplitHi(f10, f11, lp1);
                d[mt][nt][0] = __uint_as_float(lp0);   // recycle dead accum regs
                d[mt][nt][1] = __uint_as_float(lp1);
            }
        }
        if (flags & F_BLEND) {
            b0 += __shfl_xor_sync(0xffffffffu, b0, 1);
            b0 += __shfl_xor_sync(0xffffffffu, b0, 2);
            b1 += __shfl_xor_sync(0xffffffffu, b1, 1);
            b1 += __shfl_xor_sync(0xffffffffu, b1, 2);
            if (q == 0) {
                reinterpret_cast<float*>(sm + PB_OFF)[wg * 128 + r0]     = b0;
                reinterpret_cast<float*>(sm + PB_OFF)[wg * 128 + r0 + 8] = b1;
            }
        }
        if (flags & F_RGB) {
            g00 += __shfl_xor_sync(0xffffffffu, g00, 1); g00 += __shfl_xor_sync(0xffffffffu, g00, 2);
            g01 += __shfl_xor_sync(0xffffffffu, g01, 1); g01 += __shfl_xor_sync(0xffffffffu, g01, 2);
            g02 += __shfl_xor_sync(0xffffffffu, g02, 1); g02 += __shfl_xor_sync(0xffffffffu, g02, 2);
            g10 += __shfl_xor_sync(0xffffffffu, g10, 1); g10 += __shfl_xor_sync(0xffffffffu, g10, 2);
            g11 += __shfl_xor_sync(0xffffffffu, g11, 1); g11 += __shfl_xor_sync(0xffffffffu, g11, 2);
            g12 += __shfl_xor_sync(0xffffffffu, g12, 1); g12 += __shfl_xor_sync(0xffffffffu, g12, 2);
            if (q == 0) {
                float* pr = reinterpret_cast<float*>(sm + PR_OFF) + (wg * 128) * 3;
                pr[r0 * 3 + 0] = g00; pr[r0 * 3 + 1] = g01; pr[r0 * 3 + 2] = g02;
                pr[(r0 + 8) * 3 + 0] = g10; pr[(r0 + 8) * 3 + 1] = g11; pr[(r0 + 8) * 3 + 2] = g12;
            }
        }
    }

    // All mainloop reads complete block-wide before act stores.
    __syncthreads();

    if (store) {
#pragma unroll
        for (int mt = 0; mt < 2; mt++) {
            const int r0 = 32 * wm + 16 * mt + rh;
#pragma unroll
            for (int nt = 0; nt < 4; nt++) {
                char* p = sm + AHI_OFF + (uint32_t)r0 * SA + wg * 64 + nt * 16 + q * 4;
                *reinterpret_cast<uint32_t*>(p)                      = hpack[mt][nt][0];
                *reinterpret_cast<uint32_t*>(p + 8 * SA)             = hpack[mt][nt][1];
                *reinterpret_cast<uint32_t*>(p + ALO_DELTA)          = __float_as_uint(d[mt][nt][0]);
                *reinterpret_cast<uint32_t*>(p + ALO_DELTA + 8 * SA) = __float_as_uint(d[mt][nt][1]);
            }
        }
    }
}

__global__ void __launch_bounds__(BLOCK, 1)
nerf_mma_kernel(const float* __restrict__ x, const float* __restrict__ Wd2_3,
                const float* __restrict__ Wc_1, float* __restrict__ out, int N) {
    extern __shared__ char sm[];
    const uint32_t sb = smem_u32(sm);
    const int t = threadIdx.x;
    const int i0 = blockIdx.x * PTS;

    copyB_async(sb, 0, B0_OFF);

    for (int idx = t; idx < 384; idx += BLOCK)
        reinterpret_cast<float*>(sm + WC1_OFF)[idx] = Wc_1[idx];
    if (t < 128) reinterpret_cast<float*>(sm + BCOL_OFF)[t] = Wd2_3[t * 129];

    float vx = 0.f, vy = 0.f, vz = 0.f;
    if (t < PTS) {
        int i = i0 + t;
        float p0 = 0.f, p1 = 0.f, p2 = 0.f;
        if (i < N) {
            const float* xp = x + 6 * i;
            p0 = xp[0]; p1 = xp[1]; p2 = xp[2];
            vx = xp[3]; vy = xp[4]; vz = xp[5];
        }
#pragma unroll
        for (int dd = 0; dd < 3; dd++) {
            float base = (dd == 0) ? p0 : ((dd == 1) ? p1 : p2);
#pragma unroll
            for (int f = 0; f < 10; f++) {
                float s, c;
                sincosf(base * (CUDART_PI_F * (float)(1 << f)), &s, &c);
                encStore(sm, t, dd * 20 + 2 * f, s, c);
            }
        }
        encStore(sm, t, 60, 0.f, 0.f);
        encStore(sm, t, 62, 0.f, 0.f);
    }

    CP_WAIT0(); __syncthreads();
    copyB_async(sb, 1, B1_OFF);
    layerT<4, 0, 144>(sm, sb, B0_OFF, F_RELU | F_STORE);             // L1

    CP_WAIT0(); __syncthreads();
    copyB_async(sb, 2, B0_OFF);
    layerT<0, 8, 272>(sm, sb, B1_OFF, F_RELU | F_STORE);             // L2

    CP_WAIT0(); __syncthreads();
    copyB_async(sb, 3, B1_OFF);
    layerT<0, 8, 272>(sm, sb, B0_OFF, F_STORE);                      // L3 (linear)

    CP_WAIT0(); __syncthreads();
    copyB_async(sb, 4, B0_OFF);
    layerT<4, 8, 400>(sm, sb, B1_OFF, F_RELU | F_STORE);             // L4

    // enc_pos reads finished at L4's mid-barrier -> write view enc now
    if (t < PTS) {
#pragma unroll
        for (int dd = 0; dd < 3; dd++) {
            float base = (dd == 0) ? vx : ((dd == 1) ? vy : vz);
#pragma unroll
            for (int f = 0; f < 4; f++) {
                float s, c;
                sincosf(base * (CUDART_PI_F * (float)(1 << f)), &s, &c);
                encStore(sm, t, dd * 8 + 2 * f, s, c);
            }
        }
        encStore(sm, t, 24, 0.f, 0.f);
        encStore(sm, t, 26, 0.f, 0.f);
        encStore(sm, t, 28, 0.f, 0.f);
        encStore(sm, t, 30, 0.f, 0.f);
    }

    CP_WAIT0(); __syncthreads();
    copyB_async(sb, 5, B1_OFF);
    layerT<0, 8, 272>(sm, sb, B0_OFF, F_RELU | F_STORE);             // L5

    CP_WAIT0(); __syncthreads();
    copyB_async(sb, 6, B0_OFF);
    layerT<0, 8, 272>(sm, sb, B1_OFF, F_RELU | F_STORE | F_BLEND);   // L6

    CP_WAIT0(); __syncthreads();
    copyB_async(sb, 7, B1_OFF);
    layerT<0, 8, 272>(sm, sb, B0_OFF, F_STORE | F_DENS);             // L7 (linear)

    CP_WAIT0(); __syncthreads();
    layerT<2, 8, 336>(sm, sb, B1_OFF, F_RELU | F_RGB);               // L8

    __syncthreads();
    if (t < PTS) {
        int i = i0 + t;
        if (i < N) {
            const float* pr = reinterpret_cast<const float*>(sm + PR_OFF);
            const float* pb = reinterpret_cast<const float*>(sm + PB_OFF);
            float braw = pb[t] + pb[128 + t] + pb[256 + t] + pb[384 + t];
            float r0 = 0.f, r1 = 0.f, r2 = 0.f;
#pragma unroll
            for (int g = 0; g < 4; g++) {
                r0 += pr[(g * 128 + t) * 3 + 0];
                r1 += pr[(g * 128 + t) * 3 + 1];
                r2 += pr[(g * 128 + t) * 3 + 2];
            }
            float* o = out + 5 * i;
            o[0] = r0;
            o[1] = r1;
            o[2] = r2;
            o[3] = reinterpret_cast<const float*>(sm + DENS_OFF)[t];
            o[4] = 1.f / (1.f + expf(-braw));
        }
    }
}

extern "C" void kernel_launch(void* const* d_in, const int* in_sizes, int n_in,
                              void* d_out, int out_size) {
    const float* x     = (const float*)d_in[0];
    const float* Wd1_0 = (const float*)d_in[1];
    const float* Wd1_1 = (const float*)d_in[2];
    const float* Wd1_2 = (const float*)d_in[3];
    const float* Wd2_0 = (const float*)d_in[4];
    const float* Wd2_1 = (const float*)d_in[5];
    const float* Wd2_2 = (const float*)d_in[6];
    const float* Wd2_3 = (const float*)d_in[7];
    const float* Wc_0  = (const float*)d_in[8];
    const float* Wc_1  = (const float*)d_in[9];
    float* out = (float*)d_out;

    int N = in_sizes[0] / 6;
    if (N <= 0) return;

    prepass_kernel<<<(143360 + 255) / 256, 256>>>(Wd1_0, Wd1_1, Wd1_2, Wd2_0,
                                                  Wd2_1, Wd2_2, Wd2_3, Wc_0);

    cudaFuncSetAttribute(nerf_mma_kernel,
                         cudaFuncAttributeMaxDynamicSharedMemorySize, SMEM_BYTES);
    int grid = (N + PTS - 1) / PTS;
    nerf_mma_kernel<<<grid, BLOCK, SMEM_BYTES>>>(x, Wd2_3, Wc_1, out, N);
}

// round 13
// speedup vs baseline: 5.5562x; 1.1195x over previous
#include <cuda_runtime.h>
#include <cuda_fp16.h>
#include <math_constants.h>
#include <cstdint>

#define BLOCK 256
#define PTS   64

// ---- smem byte offsets (per block; 2 blocks/SM) ----
#define AHI_OFF   0         // act hi  [64][136] fp16 (stride 272B) = 17408
#define ALO_OFF   17408     // act lo
#define EHI_OFF   34816     // enc hi  [64][72] fp16 (stride 144B) = 9216
#define ELO_OFF   44032     // enc lo
#define B_OFF     53248     // weight buffer (single fp16 plane, max 200*128*2=51200)
#define WC1_OFF   104448    // Wc_1 fp32 [128][3]
#define BCOL_OFF  105984    // Wd2_3 col0 fp32 [128]
#define DENS_OFF  106496    // density fp32 [64]
#define PB_OFF    106752    // blend partials fp32 [4][64]
#define PR_OFF    107776    // rgb partials fp32 [4][64][3]
#define SMEM_BYTES 110848

#define SA 272
#define SE 144
#define ALO_DELTA 17408
#define ELO_DELTA 9216

// epilogue flag bits
#define F_RELU  1
#define F_STORE 2
#define F_DENS  4
#define F_BLEND 8
#define F_RGB   16

// ---- pre-converted weights: Bt[j][k] row-major, padded, single fp16 plane ----
__device__ __half g_w[143360];

__constant__ int c_loff[9] = {0, 9216, 26624, 44032, 69632, 87040, 104448, 121856, 143360};
__constant__ int c_kpad[8] = {72, 136, 136, 200, 136, 136, 136, 168};
__constant__ int c_n16[8]  = {1152, 2176, 2176, 3200, 2176, 2176, 2176, 2688};

__global__ void prepass_kernel(const float* __restrict__ Wd1_0, const float* __restrict__ Wd1_1,
                               const float* __restrict__ Wd1_2, const float* __restrict__ Wd2_0,
                               const float* __restrict__ Wd2_1, const float* __restrict__ Wd2_2,
                               const float* __restrict__ Wd2_3, const float* __restrict__ Wc_0) {
    int e = blockIdx.x * blockDim.x + threadIdx.x;
    if (e >= 143360) return;
    int l = 0;
    while (e >= c_loff[l + 1]) l++;
    int r = e - c_loff[l];
    int kp = c_kpad[l];
    int j = r / kp;
    int k = r % kp;
    float v = 0.f;
    switch (l) {
        case 0: if (k < 60) v = Wd1_0[k * 128 + j]; break;
        case 1: if (k < 128) v = Wd1_1[k * 128 + j]; break;
        case 2: if (k < 128) v = Wd1_2[k * 128 + j]; break;
        case 3: if (k < 60) v = Wd2_0[k * 128 + j];
                else if (k >= 64 && k < 192) v = Wd2_0[(k - 4) * 128 + j];
                break;
        case 4: if (k < 128) v = Wd2_1[k * 128 + j]; break;
        case 5: if (k < 128) v = Wd2_2[k * 128 + j]; break;
        case 6: if (k < 128) v = Wd2_3[k * 129 + (j + 1)]; break;  // rotated
        case 7: if (k < 24) v = Wc_0[k * 128 + j];
                else if (k >= 32 && k < 160) v = Wc_0[(k - 8) * 128 + j];
                break;
    }
    g_w[e] = __float2half_rn(v);
}

// ---- helpers ----
__device__ __forceinline__ void mma16816(float* d, const uint32_t* a, const uint32_t* b) {
    asm volatile(
        "mma.sync.aligned.m16n8k16.row.col.f32.f16.f16.f32 "
        "{%0,%1,%2,%3}, {%4,%5,%6,%7}, {%8,%9}, {%0,%1,%2,%3};"
        : "+f"(d[0]), "+f"(d[1]), "+f"(d[2]), "+f"(d[3])
        : "r"(a[0]), "r"(a[1]), "r"(a[2]), "r"(a[3]), "r"(b[0]), "r"(b[1]));
}

__device__ __forceinline__ void ldsm4(uint32_t* r, uint32_t addr) {
    asm volatile("ldmatrix.sync.aligned.m8n8.x4.shared.b16 {%0,%1,%2,%3}, [%4];"
                 : "=r"(r[0]), "=r"(r[1]), "=r"(r[2]), "=r"(r[3]) : "r"(addr));
}

__device__ __forceinline__ void cpasync16(uint32_t dst, const void* src) {
    asm volatile("cp.async.cg.shared.global [%0], [%1], 16;" :: "r"(dst), "l"(src));
}
#define CP_COMMIT() asm volatile("cp.async.commit_group;")
#define CP_WAIT0()  asm volatile("cp.async.wait_group 0;" ::: "memory")

__device__ __forceinline__ uint32_t smem_u32(const void* p) {
    uint32_t a;
    asm("{ .reg .u64 t; cvta.to.shared.u64 t, %1; cvt.u32.u64 %0, t; }" : "=r"(a) : "l"(p));
    return a;
}

__device__ __forceinline__ uint32_t packSplitHi(float f0, float f1, uint32_t& lp) {
    __half h0 = __float2half_rn(f0), h1 = __float2half_rn(f1);
    __half l0 = __float2half_rn(f0 - __half2float(h0));
    __half l1 = __float2half_rn(f1 - __half2float(h1));
    lp = ((uint32_t)__half_as_ushort(l1) << 16) | __half_as_ushort(l0);
    return ((uint32_t)__half_as_ushort(h1) << 16) | __half_as_ushort(h0);
}

__device__ __forceinline__ void encStore(char* sm, int row, int col, float f0, float f1) {
    uint32_t lp, hp = packSplitHi(f0, f1, lp);
    *reinterpret_cast<uint32_t*>(sm + EHI_OFF + row * SE + col * 2) = hp;
    *reinterpret_cast<uint32_t*>(sm + ELO_OFF + row * SE + col * 2) = lp;
}

__device__ __forceinline__ void copyB_async(uint32_t sb, int l) {
    const int n16 = c_n16[l];
    const char* src = reinterpret_cast<const char*>(g_w + c_loff[l]);
    const uint32_t dst = sb + B_OFF;
    for (int i = threadIdx.x; i < n16; i += BLOCK)
        cpasync16(dst + i * 16, src + i * 16);
    CP_COMMIT();
}

// One layer: EK enc k-tiles + AK act k-tiles, weight row stride SB bytes.
// 8 warps, warp tile 32 rows x 32 cols: wm = w&1 (rows 32wm..+31), wg = w>>1
// (cols 32wg..+31). 2-pass fp16: D = Ahi*B + Alo*B.
// After the mid-barrier (all B + act reads done), the NEXT layer's weight copy
// is issued into the single B buffer, overlapping stores + layer transition.
template<int EK, int AK, int SB>
__device__ __noinline__ void layerT(char* sm, uint32_t sb, int flags, int nextL) {
    const int t = threadIdx.x;
    const int w = t >> 5, lane = t & 31;
    const int wm = w & 1, wg = w >> 1;
    const int q = lane & 3, rh = lane >> 2;
    const int arow = lane & 15, asel = lane >> 4;
    const int brow = (lane & 7) + ((lane >> 4) << 3);
    const int bsel = (lane >> 3) & 1;
    constexpr int TOT = EK + AK;

    const uint32_t aHi = sb + AHI_OFF + (uint32_t)(32 * wm + arow) * SA + asel * 16;
    const uint32_t eHi = sb + EHI_OFF + (uint32_t)(32 * wm + arow) * SE + asel * 16;
    const uint32_t bB0 = sb + B_OFF + (uint32_t)(brow + wg * 32) * SB + bsel * 16;

    auto loadAhi = [&](int kt, uint32_t dst[2][4]) {
        if (kt < EK) {
            ldsm4(dst[0], eHi + kt * 32);
            ldsm4(dst[1], eHi + 16 * SE + kt * 32);
        } else {
            ldsm4(dst[0], aHi + (kt - EK) * 32);
            ldsm4(dst[1], aHi + 16 * SA + (kt - EK) * 32);
        }
    };
    auto loadAlo = [&](int kt, uint32_t dst[2][4]) {
        if (kt < EK) {
            ldsm4(dst[0], eHi + kt * 32 + ELO_DELTA);
            ldsm4(dst[1], eHi + 16 * SE + kt * 32 + ELO_DELTA);
        } else {
            ldsm4(dst[0], aHi + (kt - EK) * 32 + ALO_DELTA);
            ldsm4(dst[1], aHi + 16 * SA + (kt - EK) * 32 + ALO_DELTA);
        }
    };
    auto loadB = [&](int kt, uint32_t dst[2][4]) {
        ldsm4(dst[0], bB0 + kt * 32);
        ldsm4(dst[1], bB0 + kt * 32 + 16 * SB);
    };

    float d[2][4][4];
#pragma unroll
    for (int mt = 0; mt < 2; mt++)
#pragma unroll
        for (int nt = 0; nt < 4; nt++) {
            d[mt][nt][0] = 0.f; d[mt][nt][1] = 0.f;
            d[mt][nt][2] = 0.f; d[mt][nt][3] = 0.f;
        }

    uint32_t ah[2][2][4], bhf[2][2][4], al[2][4];
    loadAhi(0, ah[0]);
    loadB(0, bhf[0]);

#pragma unroll
    for (int kt = 0; kt < TOT; kt++) {
        const int cur = kt & 1, nxt = cur ^ 1;
        loadAlo(kt, al);
        if (kt + 1 < TOT) {
            loadAhi(kt + 1, ah[nxt]);
            loadB(kt + 1, bhf[nxt]);
        }
#pragma unroll
        for (int n2 = 0; n2 < 2; n2++)
#pragma unroll
            for (int mt = 0; mt < 2; mt++) {
                mma16816(d[mt][2 * n2],     ah[cur][mt], bhf[cur][n2]);
                mma16816(d[mt][2 * n2 + 1], ah[cur][mt], bhf[cur][n2] + 2);
            }
#pragma unroll
        for (int n2 = 0; n2 < 2; n2++)
#pragma unroll
            for (int mt = 0; mt < 2; mt++) {
                mma16816(d[mt][2 * n2],     al[mt], bhf[cur][n2]);
                mma16816(d[mt][2 * n2 + 1], al[mt], bhf[cur][n2] + 2);
            }
    }

    // ---- pre-barrier epilogue: relu (in place), aux partials, hi-pack ----
    const bool relu  = flags & F_RELU;
    const bool store = flags & F_STORE;
    const float* wc1  = reinterpret_cast<const float*>(sm + WC1_OFF);
    const float* bcol = reinterpret_cast<const float*>(sm + BCOL_OFF);
    uint32_t hpack[2][4][2];

#pragma unroll
    for (int mt = 0; mt < 2; mt++) {
        const int r0 = 32 * wm + 16 * mt + rh;
        if ((flags & F_DENS) && wg == 0 && q == 0) {
            reinterpret_cast<float*>(sm + DENS_OFF)[r0]     = d[mt][0][0];
            reinterpret_cast<float*>(sm + DENS_OFF)[r0 + 8] = d[mt][0][2];
        }
        float b0 = 0.f, b1 = 0.f;
        float g00 = 0.f, g01 = 0.f, g02 = 0.f, g10 = 0.f, g11 = 0.f, g12 = 0.f;
#pragma unroll
        for (int nt = 0; nt < 4; nt++) {
            float f00 = d[mt][nt][0], f01 = d[mt][nt][1];
            float f10 = d[mt][nt][2], f11 = d[mt][nt][3];
            if (relu) {
                f00 = fmaxf(f00, 0.f); f01 = fmaxf(f01, 0.f);
                f10 = fmaxf(f10, 0.f); f11 = fmaxf(f11, 0.f);
            }
            const int c = wg * 32 + nt * 8 + 2 * q;
            if (flags & F_BLEND) {
                b0 = fmaf(f00, bcol[c], fmaf(f01, bcol[c + 1], b0));
                b1 = fmaf(f10, bcol[c], fmaf(f11, bcol[c + 1], b1));
            }
            if (flags & F_RGB) {
                g00 = fmaf(f00, wc1[c * 3 + 0], fmaf(f01, wc1[(c + 1) * 3 + 0], g00));
                g01 = fmaf(f00, wc1[c * 3 + 1], fmaf(f01, wc1[(c + 1) * 3 + 1], g01));
                g02 = fmaf(f00, wc1[c * 3 + 2], fmaf(f01, wc1[(c + 1) * 3 + 2], g02));
                g10 = fmaf(f10, wc1[c * 3 + 0], fmaf(f11, wc1[(c + 1) * 3 + 0], g10));
                g11 = fmaf(f10, wc1[c * 3 + 1], fmaf(f11, wc1[(c + 1) * 3 + 1], g11));
                g12 = fmaf(f10, wc1[c * 3 + 2], fmaf(f11, wc1[(c + 1) * 3 + 2], g12));
            }
            if (store) {
                uint32_t lp0, lp1;
                hpack[mt][nt][0] = packSplitHi(f00, f01, lp0);
                hpack[mt][nt][1] = packSplitHi(f10, f11, lp1);
                d[mt][nt][0] = __uint_as_float(lp0);   // recycle dead accum regs
                d[mt][nt][1] = __uint_as_float(lp1);
            }
        }
        if (flags & F_BLEND) {
            b0 += __shfl_xor_sync(0xffffffffu, b0, 1);
            b0 += __shfl_xor_sync(0xffffffffu, b0, 2);
            b1 += __shfl_xor_sync(0xffffffffu, b1, 1);
            b1 += __shfl_xor_sync(0xffffffffu, b1, 2);
            if (q == 0) {
                reinterpret_cast<float*>(sm + PB_OFF)[wg * 64 + r0]     = b0;
                reinterpret_cast<float*>(sm + PB_OFF)[wg * 64 + r0 + 8] = b1;
            }
        }
        if (flags & F_RGB) {
            g00 += __shfl_xor_sync(0xffffffffu, g00, 1); g00 += __shfl_xor_sync(0xffffffffu, g00, 2);
            g01 += __shfl_xor_sync(0xffffffffu, g01, 1); g01 += __shfl_xor_sync(0xffffffffu, g01, 2);
            g02 += __shfl_xor_sync(0xffffffffu, g02, 1); g02 += __shfl_xor_sync(0xffffffffu, g02, 2);
            g10 += __shfl_xor_sync(0xffffffffu, g10, 1); g10 += __shfl_xor_sync(0xffffffffu, g10, 2);
            g11 += __shfl_xor_sync(0xffffffffu, g11, 1); g11 += __shfl_xor_sync(0xffffffffu, g11, 2);
            g12 += __shfl_xor_sync(0xffffffffu, g12, 1); g12 += __shfl_xor_sync(0xffffffffu, g12, 2);
            if (q == 0) {
                float* pr = reinterpret_cast<float*>(sm + PR_OFF) + (wg * 64) * 3;
                pr[r0 * 3 + 0] = g00; pr[r0 * 3 + 1] = g01; pr[r0 * 3 + 2] = g02;
                pr[(r0 + 8) * 3 + 0] = g10; pr[(r0 + 8) * 3 + 1] = g11; pr[(r0 + 8) * 3 + 2] = g12;
            }
        }
    }

    // All mainloop reads (act + B) complete block-wide.
    __syncthreads();

    // B buffer is now dead -> start next layer's weight copy under the stores.
    if (nextL >= 0) copyB_async(sb, nextL);

    if (store) {
#pragma unroll
        for (int mt = 0; mt < 2; mt++) {
            const int r0 = 32 * wm + 16 * mt + rh;
#pragma unroll
            for (int nt = 0; nt < 4; nt++) {
                char* p = sm + AHI_OFF + (uint32_t)r0 * SA + wg * 64 + nt * 16 + q * 4;
                *reinterpret_cast<uint32_t*>(p)                      = hpack[mt][nt][0];
                *reinterpret_cast<uint32_t*>(p + 8 * SA)             = hpack[mt][nt][1];
                *reinterpret_cast<uint32_t*>(p + ALO_DELTA)          = __float_as_uint(d[mt][nt][0]);
                *reinterpret_cast<uint32_t*>(p + ALO_DELTA + 8 * SA) = __float_as_uint(d[mt][nt][1]);
            }
        }
    }
}

__global__ void __launch_bounds__(BLOCK, 2)
nerf_mma_kernel(const float* __restrict__ x, const float* __restrict__ Wd2_3,
                const float* __restrict__ Wc_1, float* __restrict__ out, int N) {
    extern __shared__ char sm[];
    const uint32_t sb = smem_u32(sm);
    const int t = threadIdx.x;
    const int i0 = blockIdx.x * PTS;

    copyB_async(sb, 0);

    for (int idx = t; idx < 384; idx += BLOCK)
        reinterpret_cast<float*>(sm + WC1_OFF)[idx] = Wc_1[idx];
    if (t < 128) reinterpret_cast<float*>(sm + BCOL_OFF)[t] = Wd2_3[t * 129];

    float vx = 0.f, vy = 0.f, vz = 0.f;
    if (t < PTS) {
        int i = i0 + t;
        float p0 = 0.f, p1 = 0.f, p2 = 0.f;
        if (i < N) {
            const float* xp = x + 6 * i;
            p0 = xp[0]; p1 = xp[1]; p2 = xp[2];
            vx = xp[3]; vy = xp[4]; vz = xp[5];
        }
#pragma unroll
        for (int dd = 0; dd < 3; dd++) {
            float base = (dd == 0) ? p0 : ((dd == 1) ? p1 : p2);
#pragma unroll
            for (int f = 0; f < 10; f++) {
                float s, c;
                sincosf(base * (CUDART_PI_F * (float)(1 << f)), &s, &c);
                encStore(sm, t, dd * 20 + 2 * f, s, c);
            }
        }
        encStore(sm, t, 60, 0.f, 0.f);
        encStore(sm, t, 62, 0.f, 0.f);
    }

    CP_WAIT0(); __syncthreads();
    layerT<4, 0, 144>(sm, sb, F_RELU | F_STORE, 1);              // L1

    CP_WAIT0(); __syncthreads();
    layerT<0, 8, 272>(sm, sb, F_RELU | F_STORE, 2);              // L2

    CP_WAIT0(); __syncthreads();
    layerT<0, 8, 272>(sm, sb, F_STORE, 3);                       // L3 (linear)

    CP_WAIT0(); __syncthreads();
    layerT<4, 8, 400>(sm, sb, F_RELU | F_STORE, 4);              // L4

    // enc_pos reads finished at L4's mid-barrier -> write view enc now
    if (t < PTS) {
#pragma unroll
        for (int dd = 0; dd < 3; dd++) {
            float base = (dd == 0) ? vx : ((dd == 1) ? vy : vz);
#pragma unroll
            for (int f = 0; f < 4; f++) {
                float s, c;
                sincosf(base * (CUDART_PI_F * (float)(1 << f)), &s, &c);
                encStore(sm, t, dd * 8 + 2 * f, s, c);
            }
        }
        encStore(sm, t, 24, 0.f, 0.f);
        encStore(sm, t, 26, 0.f, 0.f);
        encStore(sm, t, 28, 0.f, 0.f);
        encStore(sm, t, 30, 0.f, 0.f);
    }

    CP_WAIT0(); __syncthreads();
    layerT<0, 8, 272>(sm, sb, F_RELU | F_STORE, 5);              // L5

    CP_WAIT0(); __syncthreads();
    layerT<0, 8, 272>(sm, sb, F_RELU | F_STORE | F_BLEND, 6);    // L6

    CP_WAIT0(); __syncthreads();
    layerT<0, 8, 272>(sm, sb, F_STORE | F_DENS, 7);              // L7 (linear)

    CP_WAIT0(); __syncthreads();
    layerT<2, 8, 336>(sm, sb, F_RELU | F_RGB, -1);               // L8

    __syncthreads();
    if (t < PTS) {
        int i = i0 + t;
        if (i < N) {
            const float* pr = reinterpret_cast<const float*>(sm + PR_OFF);
            const float* pb = reinterpret_cast<const float*>(sm + PB_OFF);
            float braw = pb[t] + pb[64 + t] + pb[128 + t] + pb[192 + t];
            float r0 = 0.f, r1 = 0.f, r2 = 0.f;
#pragma unroll
            for (int g = 0; g < 4; g++) {
                r0 += pr[(g * 64 + t) * 3 + 0];
                r1 += pr[(g * 64 + t) * 3 + 1];
                r2 += pr[(g * 64 + t) * 3 + 2];
            }
            float* o = out + 5 * i;
            o[0] = r0;
            o[1] = r1;
            o[2] = r2;
            o[3] = reinterpret_cast<const float*>(sm + DENS_OFF)[t];
            o[4] = 1.f / (1.f + expf(-braw));
        }
    }
}

extern "C" void kernel_launch(void* const* d_in, const int* in_sizes, int n_in,
                              void* d_out, int out_size) {
    const float* x     = (const float*)d_in[0];
    const float* Wd1_0 = (const float*)d_in[1];
    const float* Wd1_1 = (const float*)d_in[2];
    const float* Wd1_2 = (const float*)d_in[3];
    const float* Wd2_0 = (const float*)d_in[4];
    const float* Wd2_1 = (const float*)d_in[5];
    const float* Wd2_2 = (const float*)d_in[6];
    const float* Wd2_3 = (const float*)d_in[7];
    const float* Wc_0  = (const float*)d_in[8];
    const float* Wc_1  = (const float*)d_in[9];
    float* out = (float*)d_out;

    int N = in_sizes[0] / 6;
    if (N <= 0) return;

    prepass_kernel<<<(143360 + 255) / 256, 256>>>(Wd1_0, Wd1_1, Wd1_2, Wd2_0,
                                                  Wd2_1, Wd2_2, Wd2_3, Wc_0);

    cudaFuncSetAttribute(nerf_mma_kernel,
                         cudaFuncAttributeMaxDynamicSharedMemorySize, SMEM_BYTES);
    int grid = (N + PTS - 1) / PTS;
    nerf_mma_kernel<<<grid, BLOCK, SMEM_BYTES>>>(x, Wd2_3, Wc_1, out, N);
}